// round 3
// baseline (speedup 1.0000x reference)
#include <cuda_runtime.h>

typedef unsigned long long u64;

#define NBLK  128
#define NTHR  512
#define ROWS  64
#define HPAD  132
#define NSTEP 49

__device__ __forceinline__ u64 ffma2(u64 a, u64 b, u64 c) {
    u64 r;
    asm("fma.rn.f32x2 %0, %1, %2, %3;" : "=l"(r) : "l"(a), "l"(b), "l"(c));
    return r;
}
__device__ __forceinline__ float sum2(u64 v) {
    float lo, hi;
    asm("mov.b64 {%0, %1}, %2;" : "=f"(lo), "=f"(hi) : "l"(v));
    return lo + hi;
}
__device__ __forceinline__ float sigm(float x) {
    return __fdividef(1.0f, 1.0f + __expf(-x));
}
__device__ __forceinline__ float tanh_f(float x) {
    float ax = fabsf(x);
    float e  = __expf(-2.0f * ax);
    float r  = __fdividef(1.0f - e, 1.0f + e);
    return copysignf(r, x);
}

// one 128->128 encoder layer: reads ha (all rows), writes ha (own tile)
// thread: p = 4 rows {p, p+16, p+32, p+48}, t = 4 units [t*4, t*4+4)
__device__ __forceinline__ void enc_layer128(const float* __restrict__ w,
                                             const float* __restrict__ b,
                                             float* ha, int p, int t, bool relu_on) {
    float acc[4][4];
    #pragma unroll
    for (int uu = 0; uu < 4; ++uu)
        #pragma unroll
        for (int m = 0; m < 4; ++m) acc[uu][m] = 0.0f;

    const float4* w4 = (const float4*)w;   // 32 float4 per k-row
    for (int k4 = 0; k4 < 32; ++k4) {
        float xa[4][4];
        #pragma unroll
        for (int m = 0; m < 4; ++m) {
            float4 v = *(const float4*)&ha[(p + 16*m)*HPAD + k4*4];
            xa[m][0] = v.x; xa[m][1] = v.y; xa[m][2] = v.z; xa[m][3] = v.w;
        }
        #pragma unroll
        for (int kk = 0; kk < 4; ++kk) {
            float4 wv = __ldg(&w4[(k4*4 + kk)*32 + t]);
            #pragma unroll
            for (int m = 0; m < 4; ++m) {
                acc[0][m] = fmaf(wv.x, xa[m][kk], acc[0][m]);
                acc[1][m] = fmaf(wv.y, xa[m][kk], acc[1][m]);
                acc[2][m] = fmaf(wv.z, xa[m][kk], acc[2][m]);
                acc[3][m] = fmaf(wv.w, xa[m][kk], acc[3][m]);
            }
        }
    }
    __syncthreads();   // all reads of ha done
    #pragma unroll
    for (int uu = 0; uu < 4; ++uu) {
        int u = t*4 + uu;
        float bv = __ldg(&b[u]);
        #pragma unroll
        for (int m = 0; m < 4; ++m) {
            float v = acc[uu][m] + bv;
            ha[(p + 16*m)*HPAD + u] = relu_on ? fmaxf(v, 0.0f) : v;
        }
    }
    __syncthreads();
}

__global__ void __launch_bounds__(NTHR, 1)
gru_kernel(const float* __restrict__ x,
           const float* __restrict__ ew0, const float* __restrict__ eb0,
           const float* __restrict__ ew1, const float* __restrict__ eb1,
           const float* __restrict__ ew2, const float* __restrict__ eb2,
           const float* __restrict__ wih, const float* __restrict__ whh,
           const float* __restrict__ bih, const float* __restrict__ bhh,
           const float* __restrict__ dw0, const float* __restrict__ db0,
           const float* __restrict__ dw1, const float* __restrict__ db1,
           float* __restrict__ out) {
    __shared__ float ha[ROWS * HPAD];      // 8448 floats
    __shared__ float dw0t[16 * 128];       // transposed decoder w0
    __shared__ float wihs[384], bihs[384], bhhs[384];
    __shared__ float dw1s[16], db0s[16];
    __shared__ float xps[ROWS];
    __shared__ float outp[8][ROWS];
    __shared__ float db1s;

    const int tid  = threadIdx.x;
    const int p    = tid & 15;     // rows p, p+16, p+32, p+48
    const int t    = tid >> 4;     // 0..31, units [t*4, t*4+4)
    const int row0 = blockIdx.x * ROWS;

    // ---- init: small weights to smem, output col 0 = zeros, xprev = 0 ----
    for (int j = tid; j < 384; j += NTHR) {
        wihs[j] = wih[j]; bihs[j] = bih[j]; bhhs[j] = bhh[j];
    }
    for (int j = tid; j < 16*128; j += NTHR) {
        int i = j >> 7, u = j & 127;
        dw0t[j] = dw0[u*16 + i];
    }
    if (tid < 16) { dw1s[tid] = dw1[tid]; db0s[tid] = db0[tid]; }
    if (tid == 0) db1s = db1[0];
    if (tid < ROWS) {
        xps[tid] = 0.0f;
        out[(u64)(row0 + tid)*50] = 0.0f;
    }

    // ---- encoder layer 0: x[256] -> ha[128] (relu) ----
    {
        float acc[4][4];
        #pragma unroll
        for (int uu = 0; uu < 4; ++uu)
            #pragma unroll
            for (int m = 0; m < 4; ++m) acc[uu][m] = 0.0f;

        const float4* x4  = (const float4*)x;    // 64 float4 per row
        const float4* w04 = (const float4*)ew0;  // 32 float4 per k-row
        for (int k4 = 0; k4 < 64; ++k4) {
            float xa[4][4];
            #pragma unroll
            for (int m = 0; m < 4; ++m) {
                float4 v = __ldg(&x4[(u64)(row0 + p + 16*m)*64 + k4]);
                xa[m][0] = v.x; xa[m][1] = v.y; xa[m][2] = v.z; xa[m][3] = v.w;
            }
            #pragma unroll
            for (int kk = 0; kk < 4; ++kk) {
                float4 wv = __ldg(&w04[(k4*4 + kk)*32 + t]);
                #pragma unroll
                for (int m = 0; m < 4; ++m) {
                    acc[0][m] = fmaf(wv.x, xa[m][kk], acc[0][m]);
                    acc[1][m] = fmaf(wv.y, xa[m][kk], acc[1][m]);
                    acc[2][m] = fmaf(wv.z, xa[m][kk], acc[2][m]);
                    acc[3][m] = fmaf(wv.w, xa[m][kk], acc[3][m]);
                }
            }
        }
        __syncthreads();   // init smem writes complete
        #pragma unroll
        for (int uu = 0; uu < 4; ++uu) {
            int u = t*4 + uu;
            float bv = __ldg(&eb0[u]);
            #pragma unroll
            for (int m = 0; m < 4; ++m)
                ha[(p + 16*m)*HPAD + u] = fmaxf(acc[uu][m] + bv, 0.0f);
        }
        __syncthreads();
    }

    // ---- encoder layers 1 (relu) and 2 (linear) ----
    enc_layer128(ew1, eb1, ha, p, t, true);
    enc_layer128(ew2, eb2, ha, p, t, false);

    // ---- GRU + decoder, 49 steps ----
    const ulonglong2* whh2 = (const ulonglong2*)whh;  // 32 ull2 per gate-unit row
    const int drow = tid & 63;                 // decoder row
    const int ic   = tid >> 6;                 // decoder i-chunk (2 outputs of 16)

    for (int s = 0; s < NSTEP; ++s) {
        float hnew[16];

        #pragma unroll
        for (int half = 0; half < 2; ++half) {
            u64 acc2[3][2][4];                 // [gate][unit][row] - 24 u64
            #pragma unroll
            for (int g = 0; g < 3; ++g)
                #pragma unroll
                for (int uu = 0; uu < 2; ++uu)
                    #pragma unroll
                    for (int m = 0; m < 4; ++m) acc2[g][uu][m] = 0ull;

            #pragma unroll 4
            for (int k4 = 0; k4 < 32; ++k4) {
                ulonglong2 hv[4];
                #pragma unroll
                for (int m = 0; m < 4; ++m)
                    hv[m] = *(const ulonglong2*)&ha[(p + 16*m)*HPAD + k4*4];
                #pragma unroll
                for (int uu = 0; uu < 2; ++uu) {
                    int u = t*4 + half*2 + uu;
                    #pragma unroll
                    for (int g = 0; g < 3; ++g) {
                        ulonglong2 wv = __ldg(&whh2[(g*128 + u)*32 + k4]);
                        #pragma unroll
                        for (int m = 0; m < 4; ++m) {
                            acc2[g][uu][m] = ffma2(wv.x, hv[m].x, acc2[g][uu][m]);
                            acc2[g][uu][m] = ffma2(wv.y, hv[m].y, acc2[g][uu][m]);
                        }
                    }
                }
            }

            // epilogue for this half (registers + smem reads only)
            #pragma unroll
            for (int uu = 0; uu < 2; ++uu) {
                int u = t*4 + half*2 + uu;
                float wir = wihs[u], wiz = wihs[128 + u], win = wihs[256 + u];
                float br  = bihs[u]       + bhhs[u];
                float bz  = bihs[128 + u] + bhhs[128 + u];
                float bni = bihs[256 + u];
                float bnh = bhhs[256 + u];
                #pragma unroll
                for (int m = 0; m < 4; ++m) {
                    int row = p + 16*m;
                    float xp   = xps[row];
                    float hold = ha[row*HPAD + u];
                    float rg  = sigm(sum2(acc2[0][uu][m]) + fmaf(xp, wir, br));
                    float zg  = sigm(sum2(acc2[1][uu][m]) + fmaf(xp, wiz, bz));
                    float ghn = sum2(acc2[2][uu][m]) + bnh;
                    float ng  = tanh_f(fmaf(xp, win, bni) + rg * ghn);
                    hnew[half*8 + uu*4 + m] = (1.0f - zg)*ng + zg*hold;
                }
            }
        }

        __syncthreads();   // everyone finished reading old h
        #pragma unroll
        for (int half = 0; half < 2; ++half)
            #pragma unroll
            for (int uu = 0; uu < 2; ++uu)
                #pragma unroll
                for (int m = 0; m < 4; ++m)
                    ha[(p + 16*m)*HPAD + t*4 + half*2 + uu] = hnew[half*8 + uu*4 + m];
        __syncthreads();   // new h visible

        // ---- decoder: d = relu(h @ dw0 + db0); po = partial of d @ dw1 ----
        {
            const float4* hr4  = (const float4*)&ha[drow * HPAD];
            const float4* dwt4 = (const float4*)dw0t;
            float dacc[2] = {0.0f, 0.0f};
            #pragma unroll 4
            for (int k4 = 0; k4 < 32; ++k4) {
                float4 hv = hr4[k4];
                #pragma unroll
                for (int ii = 0; ii < 2; ++ii) {
                    float4 wv = dwt4[(ic*2 + ii)*32 + k4];
                    dacc[ii] = fmaf(hv.x, wv.x,
                               fmaf(hv.y, wv.y,
                               fmaf(hv.z, wv.z,
                               fmaf(hv.w, wv.w, dacc[ii]))));
                }
            }
            float po = 0.0f;
            #pragma unroll
            for (int ii = 0; ii < 2; ++ii) {
                float dv = fmaxf(dacc[ii] + db0s[ic*2 + ii], 0.0f);
                po = fmaf(dv, dw1s[ic*2 + ii], po);
            }
            outp[ic][drow] = po;
        }
        __syncthreads();

        if (tid < ROWS) {
            float o = outp[0][tid] + outp[1][tid] + outp[2][tid] + outp[3][tid]
                    + outp[4][tid] + outp[5][tid] + outp[6][tid] + outp[7][tid] + db1s;
            out[(u64)(row0 + tid)*50 + s + 1] = o;
            xps[tid] = o;
        }
        __syncthreads();   // xps ready for next step
    }
}

extern "C" void kernel_launch(void* const* d_in, const int* in_sizes, int n_in,
                              void* d_out, int out_size) {
    (void)in_sizes; (void)n_in; (void)out_size;
    const float* x   = (const float*)d_in[0];
    const float* ew0 = (const float*)d_in[1];
    const float* eb0 = (const float*)d_in[2];
    const float* ew1 = (const float*)d_in[3];
    const float* eb1 = (const float*)d_in[4];
    const float* ew2 = (const float*)d_in[5];
    const float* eb2 = (const float*)d_in[6];
    const float* wih = (const float*)d_in[7];
    const float* whh = (const float*)d_in[8];
    const float* bih = (const float*)d_in[9];
    const float* bhh = (const float*)d_in[10];
    const float* dw0 = (const float*)d_in[11];
    const float* db0 = (const float*)d_in[12];
    const float* dw1 = (const float*)d_in[13];
    const float* db1 = (const float*)d_in[14];
    float* out = (float*)d_out;

    gru_kernel<<<NBLK, NTHR>>>(x, ew0, eb0, ew1, eb1, ew2, eb2,
                               wih, whh, bih, bhh, dw0, db0, dw1, db1, out);
}

// round 4
// speedup vs baseline: 1.0348x; 1.0348x over previous
#include <cuda_runtime.h>

typedef unsigned long long u64;

#define NBLK  128
#define NTHR  512
#define ROWS  64
#define HPAD  132
#define NSTEP 49

// ---- dynamic smem layout (float offsets) ----
#define HTD_F   0            // u64 htd[128][64] dup'd hidden  (16384 floats)
#define HA_F    16384        // ha[64][132] encoder scratch    (8448)
#define DW0T_F  24832        // transposed decoder w0          (2048)
#define WIHS_F  26880        // (384)
#define BIHS_F  27264        // (384)
#define BHHS_F  27648        // (384)
#define DW1S_F  28032        // (16)
#define DB0S_F  28048        // (16)
#define XPS_F   28064        // (64)
#define OUTP_F  28128        // (8*64)
#define DB1S_F  28640        // (1)
#define SMEM_FLOATS 28644
#define SMEM_BYTES  (SMEM_FLOATS * 4)

// repacked whh: float4 idx = ((j2*3+g)*2+up)*32 + t ; contents
// (w[u0][2j2], w[u1][2j2], w[u0][2j2+1], w[u1][2j2+1]), u0 = t*4+up*2, u1 = u0+1
__device__ float g_wp[49152];

__device__ __forceinline__ u64 ffma2(u64 a, u64 b, u64 c) {
    u64 r;
    asm("fma.rn.f32x2 %0, %1, %2, %3;" : "=l"(r) : "l"(a), "l"(b), "l"(c));
    return r;
}
__device__ __forceinline__ u64 pkdup(float v) {
    u64 r;
    asm("mov.b64 %0, {%1, %1};" : "=l"(r) : "f"(v));
    return r;
}
__device__ __forceinline__ void unpk(u64 v, float& lo, float& hi) {
    asm("mov.b64 {%0, %1}, %2;" : "=f"(lo), "=f"(hi) : "l"(v));
}
__device__ __forceinline__ float sigm(float x) {
    return __fdividef(1.0f, 1.0f + __expf(-x));
}
__device__ __forceinline__ float tanh_f(float x) {
    float ax = fabsf(x);
    float e  = __expf(-2.0f * ax);
    float r  = __fdividef(1.0f - e, 1.0f + e);
    return copysignf(r, x);
}

// ---------------- weight repack kernel ----------------
__global__ void repack_whh(const float* __restrict__ whh) {
    int i = blockIdx.x * blockDim.x + threadIdx.x;   // 0..49151
    if (i >= 49152) return;
    int e  = i & 3;  int f4 = i >> 2;
    int t  = f4 & 31; int r = f4 >> 5;
    int up = r & 1;   r >>= 1;
    int g  = r % 3;   int j2 = r / 3;
    int k  = 2*j2 + (e >> 1);
    int u  = t*4 + up*2 + (e & 1);
    g_wp[i] = whh[(g*128 + u)*128 + k];
}

// ---------------- encoder helpers ----------------
// 128->128 layer: reads ha (all rows), writes ha (relu)
__device__ __forceinline__ void enc_layer128(const float* __restrict__ w,
                                             const float* __restrict__ b,
                                             float* ha, int p, int t) {
    float acc[4][4];
    #pragma unroll
    for (int uu = 0; uu < 4; ++uu)
        #pragma unroll
        for (int m = 0; m < 4; ++m) acc[uu][m] = 0.0f;

    const float4* w4 = (const float4*)w;
    for (int k4 = 0; k4 < 32; ++k4) {
        float xa[4][4];
        #pragma unroll
        for (int m = 0; m < 4; ++m) {
            float4 v = *(const float4*)&ha[(p + 16*m)*HPAD + k4*4];
            xa[m][0] = v.x; xa[m][1] = v.y; xa[m][2] = v.z; xa[m][3] = v.w;
        }
        #pragma unroll
        for (int kk = 0; kk < 4; ++kk) {
            float4 wv = __ldg(&w4[(k4*4 + kk)*32 + t]);
            #pragma unroll
            for (int m = 0; m < 4; ++m) {
                acc[0][m] = fmaf(wv.x, xa[m][kk], acc[0][m]);
                acc[1][m] = fmaf(wv.y, xa[m][kk], acc[1][m]);
                acc[2][m] = fmaf(wv.z, xa[m][kk], acc[2][m]);
                acc[3][m] = fmaf(wv.w, xa[m][kk], acc[3][m]);
            }
        }
    }
    __syncthreads();
    #pragma unroll
    for (int uu = 0; uu < 4; ++uu) {
        int u = t*4 + uu;
        float bv = __ldg(&b[u]);
        #pragma unroll
        for (int m = 0; m < 4; ++m)
            ha[(p + 16*m)*HPAD + u] = fmaxf(acc[uu][m] + bv, 0.0f);
    }
    __syncthreads();
}

// final 128->128 layer (linear): reads ha, writes htd (transposed, duplicated)
__device__ __forceinline__ void enc_layer_final(const float* __restrict__ w,
                                                const float* __restrict__ b,
                                                float* ha, u64* htd64, int p, int t) {
    float acc[4][4];
    #pragma unroll
    for (int uu = 0; uu < 4; ++uu)
        #pragma unroll
        for (int m = 0; m < 4; ++m) acc[uu][m] = 0.0f;

    const float4* w4 = (const float4*)w;
    for (int k4 = 0; k4 < 32; ++k4) {
        float xa[4][4];
        #pragma unroll
        for (int m = 0; m < 4; ++m) {
            float4 v = *(const float4*)&ha[(p + 16*m)*HPAD + k4*4];
            xa[m][0] = v.x; xa[m][1] = v.y; xa[m][2] = v.z; xa[m][3] = v.w;
        }
        #pragma unroll
        for (int kk = 0; kk < 4; ++kk) {
            float4 wv = __ldg(&w4[(k4*4 + kk)*32 + t]);
            #pragma unroll
            for (int m = 0; m < 4; ++m) {
                acc[0][m] = fmaf(wv.x, xa[m][kk], acc[0][m]);
                acc[1][m] = fmaf(wv.y, xa[m][kk], acc[1][m]);
                acc[2][m] = fmaf(wv.z, xa[m][kk], acc[2][m]);
                acc[3][m] = fmaf(wv.w, xa[m][kk], acc[3][m]);
            }
        }
    }
    __syncthreads();
    #pragma unroll
    for (int uu = 0; uu < 4; ++uu) {
        int u = t*4 + uu;
        float bv = __ldg(&b[u]);
        #pragma unroll
        for (int m = 0; m < 4; ++m) {
            float v = acc[uu][m] + bv;
            htd64[u*64 + (p + 16*m)] = pkdup(v);
        }
    }
    __syncthreads();
}

__global__ void __launch_bounds__(NTHR, 1)
gru_kernel(const float* __restrict__ x,
           const float* __restrict__ ew0, const float* __restrict__ eb0,
           const float* __restrict__ ew1, const float* __restrict__ eb1,
           const float* __restrict__ ew2, const float* __restrict__ eb2,
           const float* __restrict__ wih, const float* __restrict__ whh,
           const float* __restrict__ bih, const float* __restrict__ bhh,
           const float* __restrict__ dw0, const float* __restrict__ db0,
           const float* __restrict__ dw1, const float* __restrict__ db1,
           float* __restrict__ out) {
    extern __shared__ float sm[];
    u64*   htd64 = (u64*)(sm + HTD_F);
    float* htf   = sm + HTD_F;          // scalar view of duplicated h
    float* ha    = sm + HA_F;
    float* dw0t  = sm + DW0T_F;
    float* wihs  = sm + WIHS_F;
    float* bihs  = sm + BIHS_F;
    float* bhhs  = sm + BHHS_F;
    float* dw1s  = sm + DW1S_F;
    float* db0s  = sm + DB0S_F;
    float* xps   = sm + XPS_F;
    float* outp  = sm + OUTP_F;
    float* db1s  = sm + DB1S_F;

    const int tid  = threadIdx.x;
    const int p    = tid & 15;     // rows p+16m
    const int t    = tid >> 4;     // 0..31, units [t*4, t*4+4)
    const int row0 = blockIdx.x * ROWS;

    // ---- init small smem ----
    for (int j = tid; j < 384; j += NTHR) {
        wihs[j] = wih[j]; bihs[j] = bih[j]; bhhs[j] = bhh[j];
    }
    for (int j = tid; j < 16*128; j += NTHR) {
        int i = j >> 7, u = j & 127;
        dw0t[j] = dw0[u*16 + i];
    }
    if (tid < 16) { dw1s[tid] = dw1[tid]; db0s[tid] = db0[tid]; }
    if (tid == 0) db1s[0] = db1[0];
    if (tid < ROWS) {
        xps[tid] = 0.0f;
        out[(u64)(row0 + tid)*50] = 0.0f;
    }

    // ---- encoder layer 0: x[256] -> ha[128] (relu) ----
    {
        float acc[4][4];
        #pragma unroll
        for (int uu = 0; uu < 4; ++uu)
            #pragma unroll
            for (int m = 0; m < 4; ++m) acc[uu][m] = 0.0f;

        const float4* x4  = (const float4*)x;
        const float4* w04 = (const float4*)ew0;
        for (int k4 = 0; k4 < 64; ++k4) {
            float xa[4][4];
            #pragma unroll
            for (int m = 0; m < 4; ++m) {
                float4 v = __ldg(&x4[(u64)(row0 + p + 16*m)*64 + k4]);
                xa[m][0] = v.x; xa[m][1] = v.y; xa[m][2] = v.z; xa[m][3] = v.w;
            }
            #pragma unroll
            for (int kk = 0; kk < 4; ++kk) {
                float4 wv = __ldg(&w04[(k4*4 + kk)*32 + t]);
                #pragma unroll
                for (int m = 0; m < 4; ++m) {
                    acc[0][m] = fmaf(wv.x, xa[m][kk], acc[0][m]);
                    acc[1][m] = fmaf(wv.y, xa[m][kk], acc[1][m]);
                    acc[2][m] = fmaf(wv.z, xa[m][kk], acc[2][m]);
                    acc[3][m] = fmaf(wv.w, xa[m][kk], acc[3][m]);
                }
            }
        }
        __syncthreads();
        #pragma unroll
        for (int uu = 0; uu < 4; ++uu) {
            int u = t*4 + uu;
            float bv = __ldg(&eb0[u]);
            #pragma unroll
            for (int m = 0; m < 4; ++m)
                ha[(p + 16*m)*HPAD + u] = fmaxf(acc[uu][m] + bv, 0.0f);
        }
        __syncthreads();
    }

    enc_layer128(ew1, eb1, ha, p, t);
    enc_layer_final(ew2, eb2, ha, htd64, p, t);

    // ---- GRU + decoder, 49 steps ----
    const ulonglong2* wp2 = (const ulonglong2*)g_wp;  // same bits as float4 layout
    const int drow = tid & 63;
    const int ic   = tid >> 6;      // 0..7, 2 decoder outputs each

    for (int s = 0; s < NSTEP; ++s) {
        // accumulate gh = h @ whh^T, unit-pairs packed in u64 halves
        u64 acc[3][2][4];           // [gate][unit-pair][row] = (sum_u0, sum_u1)
        #pragma unroll
        for (int g = 0; g < 3; ++g)
            #pragma unroll
            for (int up = 0; up < 2; ++up)
                #pragma unroll
                for (int m = 0; m < 4; ++m) acc[g][up][m] = 0ull;

        #pragma unroll 2
        for (int j2 = 0; j2 < 64; ++j2) {
            int k0 = 2*j2;
            u64 hv0[4], hv1[4];     // duplicated h values, rows p+16m
            #pragma unroll
            for (int m = 0; m < 4; ++m) {
                hv0[m] = htd64[k0*64       + p + 16*m];
                hv1[m] = htd64[(k0 + 1)*64 + p + 16*m];
            }
            #pragma unroll
            for (int up = 0; up < 2; ++up) {
                #pragma unroll
                for (int g = 0; g < 3; ++g) {
                    ulonglong2 wv = __ldg(&wp2[((j2*3 + g)*2 + up)*32 + t]);
                    #pragma unroll
                    for (int m = 0; m < 4; ++m) {
                        acc[g][up][m] = ffma2(wv.x, hv0[m], acc[g][up][m]);
                        acc[g][up][m] = ffma2(wv.y, hv1[m], acc[g][up][m]);
                    }
                }
            }
        }

        // epilogue: activations + new hidden (old h still in smem)
        float hnew[16];             // [(up*2+i)*4 + m]
        #pragma unroll
        for (int up = 0; up < 2; ++up) {
            #pragma unroll
            for (int m = 0; m < 4; ++m) {
                int r = p + 16*m;
                float xp = xps[r];
                float gr0, gr1, gz0, gz1, gn0, gn1;
                unpk(acc[0][up][m], gr0, gr1);
                unpk(acc[1][up][m], gz0, gz1);
                unpk(acc[2][up][m], gn0, gn1);
                #pragma unroll
                for (int i = 0; i < 2; ++i) {
                    int u = t*4 + up*2 + i;
                    float gr = i ? gr1 : gr0;
                    float gz = i ? gz1 : gz0;
                    float gn = i ? gn1 : gn0;
                    float wir = wihs[u], wiz = wihs[128 + u], win = wihs[256 + u];
                    float br  = bihs[u]       + bhhs[u];
                    float bz  = bihs[128 + u] + bhhs[128 + u];
                    float bni = bihs[256 + u];
                    float bnh = bhhs[256 + u];
                    float hold = htf[(u*64 + r)*2];
                    float rg = sigm(gr + fmaf(xp, wir, br));
                    float zg = sigm(gz + fmaf(xp, wiz, bz));
                    float ng = tanh_f(fmaf(xp, win, bni) + rg*(gn + bnh));
                    hnew[(up*2 + i)*4 + m] = (1.0f - zg)*ng + zg*hold;
                }
            }
        }

        __syncthreads();   // everyone finished reading old h
        #pragma unroll
        for (int up = 0; up < 2; ++up)
            #pragma unroll
            for (int i = 0; i < 2; ++i)
                #pragma unroll
                for (int m = 0; m < 4; ++m)
                    htd64[(t*4 + up*2 + i)*64 + p + 16*m] = pkdup(hnew[(up*2 + i)*4 + m]);
        __syncthreads();   // new h visible

        // ---- decoder ----
        {
            const float4* dwt4 = (const float4*)dw0t;
            float dacc[2] = {0.0f, 0.0f};
            #pragma unroll 4
            for (int k4 = 0; k4 < 32; ++k4) {
                float hvv[4];
                #pragma unroll
                for (int kk = 0; kk < 4; ++kk)
                    hvv[kk] = htf[((k4*4 + kk)*64 + drow)*2];
                #pragma unroll
                for (int ii = 0; ii < 2; ++ii) {
                    float4 wv = dwt4[(ic*2 + ii)*32 + k4];
                    dacc[ii] = fmaf(hvv[0], wv.x,
                               fmaf(hvv[1], wv.y,
                               fmaf(hvv[2], wv.z,
                               fmaf(hvv[3], wv.w, dacc[ii]))));
                }
            }
            float po = 0.0f;
            #pragma unroll
            for (int ii = 0; ii < 2; ++ii) {
                float dv = fmaxf(dacc[ii] + db0s[ic*2 + ii], 0.0f);
                po = fmaf(dv, dw1s[ic*2 + ii], po);
            }
            outp[ic*ROWS + drow] = po;
        }
        __syncthreads();

        if (tid < ROWS) {
            float o = db1s[0];
            #pragma unroll
            for (int c = 0; c < 8; ++c) o += outp[c*ROWS + tid];
            out[(u64)(row0 + tid)*50 + s + 1] = o;
            xps[tid] = o;
        }
        __syncthreads();
    }
}

extern "C" void kernel_launch(void* const* d_in, const int* in_sizes, int n_in,
                              void* d_out, int out_size) {
    (void)in_sizes; (void)n_in; (void)out_size;
    const float* x   = (const float*)d_in[0];
    const float* ew0 = (const float*)d_in[1];
    const float* eb0 = (const float*)d_in[2];
    const float* ew1 = (const float*)d_in[3];
    const float* eb1 = (const float*)d_in[4];
    const float* ew2 = (const float*)d_in[5];
    const float* eb2 = (const float*)d_in[6];
    const float* wih = (const float*)d_in[7];
    const float* whh = (const float*)d_in[8];
    const float* bih = (const float*)d_in[9];
    const float* bhh = (const float*)d_in[10];
    const float* dw0 = (const float*)d_in[11];
    const float* db0 = (const float*)d_in[12];
    const float* dw1 = (const float*)d_in[13];
    const float* db1 = (const float*)d_in[14];
    float* out = (float*)d_out;

    cudaFuncSetAttribute(gru_kernel, cudaFuncAttributeMaxDynamicSharedMemorySize, SMEM_BYTES);

    repack_whh<<<96, 512>>>(whh);
    gru_kernel<<<NBLK, NTHR, SMEM_BYTES>>>(x, ew0, eb0, ew1, eb1, ew2, eb2,
                                           wih, whh, bih, bhh, dw0, db0, dw1, db1, out);
}

// round 6
// speedup vs baseline: 2.4809x; 2.3976x over previous
#include <cuda_runtime.h>
#include <cuda_bf16.h>

typedef unsigned int u32;
typedef unsigned long long u64;

#define NBLK  128
#define NTHR  512
#define ROWS  64
#define HPAD  132
#define NSTEP 49

// ---- dynamic smem layout (float offsets) ----
#define F_XPS   0        // 64
#define F_OUTP  64       // 8*64
#define F_WIHS  576      // 384
#define F_BIHS  960      // 384
#define F_BHHS  1344     // 384
#define F_DW1   1728     // 16
#define F_DB0   1744     // 16
#define F_DB1   1760     // 1
#define F_DW0T  1792     // 16*128
#define F_HT    3840     // 128*65  hT[u][r]
#define F_HHI   12160    // bf16 [64][136] = 4352 floats
#define F_HLO   16512    // 4352
#define F_HA    20864    // 64*132 encoder scratch
#define SMEM_FLOATS 29312
#define SMEM_BYTES  (SMEM_FLOATS*4)

// A fragments, exact mma layout: [prec][g][wm][k][lane] as uint4
__device__ uint4 g_wfrag[2 * 3 * 8 * 8 * 32];

#define MMA(c, a, b0v, b1v) asm volatile( \
    "mma.sync.aligned.m16n8k16.row.col.f32.bf16.bf16.f32 " \
    "{%0,%1,%2,%3}, {%4,%5,%6,%7}, {%8,%9}, {%0,%1,%2,%3};" \
    : "+f"((c)[0]), "+f"((c)[1]), "+f"((c)[2]), "+f"((c)[3]) \
    : "r"((a).x), "r"((a).y), "r"((a).z), "r"((a).w), "r"(b0v), "r"(b1v))

__device__ __forceinline__ float sigm(float x) {
    return __fdividef(1.0f, 1.0f + __expf(-x));
}
__device__ __forceinline__ float tanh_f(float x) {
    float ax = fabsf(x);
    float e  = __expf(-2.0f * ax);
    float r  = __fdividef(1.0f - e, 1.0f + e);
    return copysignf(r, x);
}
__device__ __forceinline__ u32 pack_bf2(__nv_bfloat16 lo, __nv_bfloat16 hi) {
    return ((u32)__bfloat16_as_ushort(hi) << 16) | (u32)__bfloat16_as_ushort(lo);
}

// ---------------- weight repack: whh[384][128] -> mma A fragments (hi/lo split) ----
__global__ void repack(const float* __restrict__ whh) {
    int idx = blockIdx.x * blockDim.x + threadIdx.x;
    if (idx >= 12288) return;
    int lane = idx & 31;
    int k    = (idx >> 5) & 7;
    int wm   = (idx >> 8) & 7;
    int gp   = idx >> 11;          // 0..5
    int g    = gp % 3;
    int prec = gp / 3;
    int row  = g * 128 + wm * 16 + (lane >> 2);
    int k0   = k * 16 + (lane & 3) * 2;

    u32 out[4];
    #pragma unroll
    for (int q = 0; q < 4; ++q) {
        int rr = row + 8 * (q & 1);
        int kk = k0 + 8 * (q >> 1);
        float v0 = whh[rr * 128 + kk];
        float v1 = whh[rr * 128 + kk + 1];
        __nv_bfloat16 h0 = __float2bfloat16(v0);
        __nv_bfloat16 h1 = __float2bfloat16(v1);
        if (prec == 0) {
            out[q] = pack_bf2(h0, h1);
        } else {
            out[q] = pack_bf2(__float2bfloat16(v0 - __bfloat162float(h0)),
                              __float2bfloat16(v1 - __bfloat162float(h1)));
        }
    }
    g_wfrag[idx] = make_uint4(out[0], out[1], out[2], out[3]);
}

// one 128->128 encoder layer (reads/writes ha), scalar fp32
__device__ __forceinline__ void enc_layer128(const float* __restrict__ w,
                                             const float* __restrict__ b,
                                             float* ha, int p, int t, bool relu_on) {
    float acc[4][4];
    #pragma unroll
    for (int uu = 0; uu < 4; ++uu)
        #pragma unroll
        for (int m = 0; m < 4; ++m) acc[uu][m] = 0.0f;
    const float4* w4 = (const float4*)w;
    for (int k4 = 0; k4 < 32; ++k4) {
        float xa[4][4];
        #pragma unroll
        for (int m = 0; m < 4; ++m) {
            float4 v = *(const float4*)&ha[(p + 16*m)*HPAD + k4*4];
            xa[m][0] = v.x; xa[m][1] = v.y; xa[m][2] = v.z; xa[m][3] = v.w;
        }
        #pragma unroll
        for (int kk = 0; kk < 4; ++kk) {
            float4 wv = __ldg(&w4[(k4*4 + kk)*32 + t]);
            #pragma unroll
            for (int m = 0; m < 4; ++m) {
                acc[0][m] = fmaf(wv.x, xa[m][kk], acc[0][m]);
                acc[1][m] = fmaf(wv.y, xa[m][kk], acc[1][m]);
                acc[2][m] = fmaf(wv.z, xa[m][kk], acc[2][m]);
                acc[3][m] = fmaf(wv.w, xa[m][kk], acc[3][m]);
            }
        }
    }
    __syncthreads();
    #pragma unroll
    for (int uu = 0; uu < 4; ++uu) {
        int u = t*4 + uu;
        float bv = __ldg(&b[u]);
        #pragma unroll
        for (int m = 0; m < 4; ++m) {
            float v = acc[uu][m] + bv;
            ha[(p + 16*m)*HPAD + u] = relu_on ? fmaxf(v, 0.0f) : v;
        }
    }
    __syncthreads();
}

__global__ void __launch_bounds__(NTHR, 1)
gru_kernel(const float* __restrict__ x,
           const float* __restrict__ ew0, const float* __restrict__ eb0,
           const float* __restrict__ ew1, const float* __restrict__ eb1,
           const float* __restrict__ ew2, const float* __restrict__ eb2,
           const float* __restrict__ wih, const float* __restrict__ whh,
           const float* __restrict__ bih, const float* __restrict__ bhh,
           const float* __restrict__ dw0, const float* __restrict__ db0,
           const float* __restrict__ dw1, const float* __restrict__ db1,
           float* __restrict__ out) {
    extern __shared__ float sm[];
    float* xps  = sm + F_XPS;
    float* outp = sm + F_OUTP;
    float* wihs = sm + F_WIHS;
    float* bihs = sm + F_BIHS;
    float* bhhs = sm + F_BHHS;
    float* dw1s = sm + F_DW1;
    float* db0s = sm + F_DB0;
    float* dw0t = sm + F_DW0T;
    float* hT   = sm + F_HT;                 // hT[u*65 + r]
    char*  hhi  = (char*)(sm + F_HHI);       // bf16 [r][136]
    char*  hlo  = (char*)(sm + F_HLO);
    float* ha   = sm + F_HA;

    const int tid  = threadIdx.x;
    const int wid  = tid >> 5;
    const int lane = tid & 31;
    const int row0 = blockIdx.x * ROWS;

    // ---- small smem init ----
    for (int j = tid; j < 384; j += NTHR) {
        wihs[j] = wih[j]; bihs[j] = bih[j]; bhhs[j] = bhh[j];
    }
    for (int j = tid; j < 16*128; j += NTHR) {
        int i = j >> 7, k = j & 127;
        dw0t[j] = dw0[k*16 + i];
    }
    if (tid < 16) { dw1s[tid] = dw1[tid]; db0s[tid] = db0[tid]; }
    if (tid == 0) sm[F_DB1] = db1[0];
    if (tid < ROWS) {
        xps[tid] = 0.0f;
        out[(u64)(row0 + tid)*50] = 0.0f;
    }

    // ---- encoder (scalar fp32, verified path) ----
    {
        const int p = tid & 15, t = tid >> 4;
        float acc[4][4];
        #pragma unroll
        for (int uu = 0; uu < 4; ++uu)
            #pragma unroll
            for (int m = 0; m < 4; ++m) acc[uu][m] = 0.0f;
        const float4* x4  = (const float4*)x;
        const float4* w04 = (const float4*)ew0;
        for (int k4 = 0; k4 < 64; ++k4) {
            float xa[4][4];
            #pragma unroll
            for (int m = 0; m < 4; ++m) {
                float4 v = __ldg(&x4[(u64)(row0 + p + 16*m)*64 + k4]);
                xa[m][0] = v.x; xa[m][1] = v.y; xa[m][2] = v.z; xa[m][3] = v.w;
            }
            #pragma unroll
            for (int kk = 0; kk < 4; ++kk) {
                float4 wv = __ldg(&w04[(k4*4 + kk)*32 + t]);
                #pragma unroll
                for (int m = 0; m < 4; ++m) {
                    acc[0][m] = fmaf(wv.x, xa[m][kk], acc[0][m]);
                    acc[1][m] = fmaf(wv.y, xa[m][kk], acc[1][m]);
                    acc[2][m] = fmaf(wv.z, xa[m][kk], acc[2][m]);
                    acc[3][m] = fmaf(wv.w, xa[m][kk], acc[3][m]);
                }
            }
        }
        __syncthreads();
        #pragma unroll
        for (int uu = 0; uu < 4; ++uu) {
            int u = t*4 + uu;
            float bv = __ldg(&eb0[u]);
            #pragma unroll
            for (int m = 0; m < 4; ++m)
                ha[(p + 16*m)*HPAD + u] = fmaxf(acc[uu][m] + bv, 0.0f);
        }
        __syncthreads();
        enc_layer128(ew1, eb1, ha, p, t, true);
        enc_layer128(ew2, eb2, ha, p, t, false);
    }

    // ---- h0: ha -> hT + bf16 hi/lo tiles ----
    for (int j = tid; j < 8192; j += NTHR) {
        int r = j >> 7, u = j & 127;
        float v = ha[r*HPAD + u];
        hT[u*65 + r] = v;
        __nv_bfloat16 bh = __float2bfloat16(v);
        __nv_bfloat16 bl = __float2bfloat16(v - __bfloat162float(bh));
        *(__nv_bfloat16*)(hhi + r*272 + u*2) = bh;
        *(__nv_bfloat16*)(hlo + r*272 + u*2) = bl;
    }
    __syncthreads();

    // ---- GRU + decoder, 49 steps ----
    const int wm = wid & 7;        // unit block: units wm*16 .. wm*16+15 (all 3 gates)
    const int wn = wid >> 3;       // row half: rows wn*32 .. wn*32+31
    const int drow = tid & 63, ic = tid >> 6;
    const uint4* wf = g_wfrag;

    for (int s = 0; s < NSTEP; ++s) {
        float acc[3][4][4];
        #pragma unroll
        for (int g = 0; g < 3; ++g)
            #pragma unroll
            for (int nt = 0; nt < 4; ++nt)
                #pragma unroll
                for (int q = 0; q < 4; ++q) acc[g][nt][q] = 0.0f;

        #pragma unroll 2
        for (int k = 0; k < 8; ++k) {
            u32 bh[4][2], bl[4][2];
            #pragma unroll
            for (int nt = 0; nt < 4; ++nt) {
                int r = wn*32 + nt*8 + (lane >> 2);
                int off = r*272 + k*32 + (lane & 3)*4;
                bh[nt][0] = *(const u32*)(hhi + off);
                bh[nt][1] = *(const u32*)(hhi + off + 16);
                bl[nt][0] = *(const u32*)(hlo + off);
                bl[nt][1] = *(const u32*)(hlo + off + 16);
            }
            #pragma unroll
            for (int g = 0; g < 3; ++g) {
                uint4 ah = __ldg(&wf[(g*8 + wm)*256 + k*32 + lane]);
                uint4 al = __ldg(&wf[6144 + (g*8 + wm)*256 + k*32 + lane]);
                #pragma unroll
                for (int nt = 0; nt < 4; ++nt) {
                    MMA(acc[g][nt], ah, bh[nt][0], bh[nt][1]);
                    MMA(acc[g][nt], ah, bl[nt][0], bl[nt][1]);
                    MMA(acc[g][nt], al, bh[nt][0], bh[nt][1]);
                }
            }
        }

        __syncthreads();   // all mma reads of h tiles complete

        // ---- epilogue: register-resident gate triples ----
        #pragma unroll
        for (int i = 0; i < 2; ++i) {
            int u = wm*16 + (lane >> 2) + 8*i;
            float wir = wihs[u], wiz = wihs[128 + u], win = wihs[256 + u];
            float br  = bihs[u]       + bhhs[u];
            float bz  = bihs[128 + u] + bhhs[128 + u];
            float bni = bihs[256 + u];
            float bnh = bhhs[256 + u];
            #pragma unroll
            for (int nt = 0; nt < 4; ++nt) {
                #pragma unroll
                for (int j = 0; j < 2; ++j) {
                    int r = wn*32 + nt*8 + (lane & 3)*2 + j;
                    int q = 2*i + j;
                    float xp   = xps[r];
                    float hold = hT[u*65 + r];
                    float rg = sigm(acc[0][nt][q] + fmaf(xp, wir, br));
                    float zg = sigm(acc[1][nt][q] + fmaf(xp, wiz, bz));
                    float ng = tanh_f(fmaf(xp, win, bni) + rg*(acc[2][nt][q] + bnh));
                    float h  = (1.0f - zg)*ng + zg*hold;
                    hT[u*65 + r] = h;
                    __nv_bfloat16 bhv = __float2bfloat16(h);
                    __nv_bfloat16 blv = __float2bfloat16(h - __bfloat162float(bhv));
                    *(__nv_bfloat16*)(hhi + r*272 + u*2) = bhv;
                    *(__nv_bfloat16*)(hlo + r*272 + u*2) = blv;
                }
            }
        }
        __syncthreads();   // new h visible everywhere

        // ---- decoder: relu(h @ dw0 + db0) @ dw1 (fp32 exact) ----
        {
            float d0 = 0.0f, d1 = 0.0f;
            const float* w0a = &dw0t[(ic*2 + 0)*128];
            const float* w0b = &dw0t[(ic*2 + 1)*128];
            #pragma unroll 8
            for (int k = 0; k < 128; ++k) {
                float hv = hT[k*65 + drow];
                d0 = fmaf(hv, w0a[k], d0);
                d1 = fmaf(hv, w0b[k], d1);
            }
            float po = fmaxf(d0 + db0s[ic*2], 0.0f) * dw1s[ic*2]
                     + fmaxf(d1 + db0s[ic*2 + 1], 0.0f) * dw1s[ic*2 + 1];
            outp[ic*ROWS + drow] = po;
        }
        __syncthreads();

        if (tid < ROWS) {
            float o = sm[F_DB1];
            #pragma unroll
            for (int c = 0; c < 8; ++c) o += outp[c*ROWS + tid];
            out[(u64)(row0 + tid)*50 + s + 1] = o;
            xps[tid] = o;
        }
        __syncthreads();
    }
}

extern "C" void kernel_launch(void* const* d_in, const int* in_sizes, int n_in,
                              void* d_out, int out_size) {
    (void)in_sizes; (void)n_in; (void)out_size;
    const float* x   = (const float*)d_in[0];
    const float* ew0 = (const float*)d_in[1];
    const float* eb0 = (const float*)d_in[2];
    const float* ew1 = (const float*)d_in[3];
    const float* eb1 = (const float*)d_in[4];
    const float* ew2 = (const float*)d_in[5];
    const float* eb2 = (const float*)d_in[6];
    const float* wih = (const float*)d_in[7];
    const float* whh = (const float*)d_in[8];
    const float* bih = (const float*)d_in[9];
    const float* bhh = (const float*)d_in[10];
    const float* dw0 = (const float*)d_in[11];
    const float* db0 = (const float*)d_in[12];
    const float* dw1 = (const float*)d_in[13];
    const float* db1 = (const float*)d_in[14];
    float* out = (float*)d_out;

    cudaFuncSetAttribute(gru_kernel, cudaFuncAttributeMaxDynamicSharedMemorySize, SMEM_BYTES);

    repack<<<24, 512>>>(whh);
    gru_kernel<<<NBLK, NTHR, SMEM_BYTES>>>(x, ew0, eb0, ew1, eb1, ew2, eb2,
                                           wih, whh, bih, bhh, dw0, db0, dw1, db1, out);
}

// round 7
// speedup vs baseline: 2.9010x; 1.1693x over previous
#include <cuda_runtime.h>
#include <cuda_bf16.h>

typedef unsigned int u32;
typedef unsigned long long u64;

#define NBLK  128
#define NTHR  512
#define ROWS  64
#define HPAD  132
#define NSTEP 49

// ---- dynamic smem layout (float offsets) ----
#define F_XPS   0        // 64
#define F_WIHS  64       // 384
#define F_BIHS  448      // 384
#define F_BHHS  832      // 384
#define F_DW1   1216     // 16
#define F_DB0   1232     // 16
#define F_DB1   1248     // 1 (pad to 1280)
#define F_HHI   1280     // bf16 [64][136] = 4352 floats
#define F_HLO   5632     // 4352
#define F_HS    9984     // 16*512 per-thread hold slots
#define F_HA    18176    // 64*132 encoder scratch
#define SMEM_FLOATS 26624
#define SMEM_BYTES  (SMEM_FLOATS*4)

// GRU A fragments: [prec][g][wm][k][lane] as uint4
__device__ uint4 g_wfrag[2 * 3 * 8 * 8 * 32];
// decoder A fragments: [prec][k][lane] as uint4 (m16 x k128)
__device__ uint4 g_dfrag[2 * 8 * 32];

#define MMA(c, a, b0v, b1v) asm volatile( \
    "mma.sync.aligned.m16n8k16.row.col.f32.bf16.bf16.f32 " \
    "{%0,%1,%2,%3}, {%4,%5,%6,%7}, {%8,%9}, {%0,%1,%2,%3};" \
    : "+f"((c)[0]), "+f"((c)[1]), "+f"((c)[2]), "+f"((c)[3]) \
    : "r"((a).x), "r"((a).y), "r"((a).z), "r"((a).w), "r"(b0v), "r"(b1v))

__device__ __forceinline__ float sigm(float x) {
    return __fdividef(1.0f, 1.0f + __expf(-x));
}
__device__ __forceinline__ float tanh_f(float x) {
    float ax = fabsf(x);
    float e  = __expf(-2.0f * ax);
    float r  = __fdividef(1.0f - e, 1.0f + e);
    return copysignf(r, x);
}
__device__ __forceinline__ u32 pack_bf2(__nv_bfloat16 lo, __nv_bfloat16 hi) {
    return ((u32)__bfloat16_as_ushort(hi) << 16) | (u32)__bfloat16_as_ushort(lo);
}

// ---------------- weight repack ----------------
__global__ void repack(const float* __restrict__ whh, const float* __restrict__ dw0) {
    int idx = blockIdx.x * blockDim.x + threadIdx.x;
    if (idx < 12288) {
        // GRU whh fragments
        int lane = idx & 31;
        int k    = (idx >> 5) & 7;
        int wm   = (idx >> 8) & 7;
        int gp   = idx >> 11;          // 0..5
        int g    = gp % 3;
        int prec = gp / 3;
        int row  = g * 128 + wm * 16 + (lane >> 2);
        int k0   = k * 16 + (lane & 3) * 2;
        u32 o[4];
        #pragma unroll
        for (int q = 0; q < 4; ++q) {
            int rr = row + 8 * (q & 1);
            int kk = k0 + 8 * (q >> 1);
            float v0 = whh[rr * 128 + kk];
            float v1 = whh[rr * 128 + kk + 1];
            __nv_bfloat16 h0 = __float2bfloat16(v0);
            __nv_bfloat16 h1 = __float2bfloat16(v1);
            if (prec == 0) o[q] = pack_bf2(h0, h1);
            else o[q] = pack_bf2(__float2bfloat16(v0 - __bfloat162float(h0)),
                                 __float2bfloat16(v1 - __bfloat162float(h1)));
        }
        g_wfrag[idx] = make_uint4(o[0], o[1], o[2], o[3]);
    } else if (idx < 12800) {
        // decoder dw0 fragments: A[i][k] = dw0[k*16 + i], m16 tile
        int local = idx - 12288;
        int lane = local & 31;
        int k    = (local >> 5) & 7;
        int prec = local >> 8;
        int row  = lane >> 2;
        int k0   = k * 16 + (lane & 3) * 2;
        u32 o[4];
        #pragma unroll
        for (int q = 0; q < 4; ++q) {
            int rr = row + 8 * (q & 1);
            int kk = k0 + 8 * (q >> 1);
            float v0 = dw0[kk * 16 + rr];
            float v1 = dw0[(kk + 1) * 16 + rr];
            __nv_bfloat16 h0 = __float2bfloat16(v0);
            __nv_bfloat16 h1 = __float2bfloat16(v1);
            if (prec == 0) o[q] = pack_bf2(h0, h1);
            else o[q] = pack_bf2(__float2bfloat16(v0 - __bfloat162float(h0)),
                                 __float2bfloat16(v1 - __bfloat162float(h1)));
        }
        g_dfrag[local] = make_uint4(o[0], o[1], o[2], o[3]);
    }
}

// one 128->128 encoder layer (reads/writes ha), scalar fp32
__device__ __forceinline__ void enc_layer128(const float* __restrict__ w,
                                             const float* __restrict__ b,
                                             float* ha, int p, int t, bool relu_on) {
    float acc[4][4];
    #pragma unroll
    for (int uu = 0; uu < 4; ++uu)
        #pragma unroll
        for (int m = 0; m < 4; ++m) acc[uu][m] = 0.0f;
    const float4* w4 = (const float4*)w;
    for (int k4 = 0; k4 < 32; ++k4) {
        float xa[4][4];
        #pragma unroll
        for (int m = 0; m < 4; ++m) {
            float4 v = *(const float4*)&ha[(p + 16*m)*HPAD + k4*4];
            xa[m][0] = v.x; xa[m][1] = v.y; xa[m][2] = v.z; xa[m][3] = v.w;
        }
        #pragma unroll
        for (int kk = 0; kk < 4; ++kk) {
            float4 wv = __ldg(&w4[(k4*4 + kk)*32 + t]);
            #pragma unroll
            for (int m = 0; m < 4; ++m) {
                acc[0][m] = fmaf(wv.x, xa[m][kk], acc[0][m]);
                acc[1][m] = fmaf(wv.y, xa[m][kk], acc[1][m]);
                acc[2][m] = fmaf(wv.z, xa[m][kk], acc[2][m]);
                acc[3][m] = fmaf(wv.w, xa[m][kk], acc[3][m]);
            }
        }
    }
    __syncthreads();
    #pragma unroll
    for (int uu = 0; uu < 4; ++uu) {
        int u = t*4 + uu;
        float bv = __ldg(&b[u]);
        #pragma unroll
        for (int m = 0; m < 4; ++m) {
            float v = acc[uu][m] + bv;
            ha[(p + 16*m)*HPAD + u] = relu_on ? fmaxf(v, 0.0f) : v;
        }
    }
    __syncthreads();
}

__global__ void __launch_bounds__(NTHR, 1)
gru_kernel(const float* __restrict__ x,
           const float* __restrict__ ew0, const float* __restrict__ eb0,
           const float* __restrict__ ew1, const float* __restrict__ eb1,
           const float* __restrict__ ew2, const float* __restrict__ eb2,
           const float* __restrict__ wih, const float* __restrict__ whh,
           const float* __restrict__ bih, const float* __restrict__ bhh,
           const float* __restrict__ dw0, const float* __restrict__ db0,
           const float* __restrict__ dw1, const float* __restrict__ db1,
           float* __restrict__ out) {
    extern __shared__ float sm[];
    float* xps  = sm + F_XPS;
    float* wihs = sm + F_WIHS;
    float* bihs = sm + F_BIHS;
    float* bhhs = sm + F_BHHS;
    float* dw1s = sm + F_DW1;
    float* db0s = sm + F_DB0;
    char*  hhi  = (char*)(sm + F_HHI);   // bf16 [r][136]
    char*  hlo  = (char*)(sm + F_HLO);
    float* hs   = sm + F_HS;             // hold slots [16][512]
    float* ha   = sm + F_HA;

    const int tid  = threadIdx.x;
    const int wid  = tid >> 5;
    const int lane = tid & 31;
    const int row0 = blockIdx.x * ROWS;

    // ---- small smem init ----
    for (int j = tid; j < 384; j += NTHR) {
        wihs[j] = wih[j]; bihs[j] = bih[j]; bhhs[j] = bhh[j];
    }
    if (tid < 16) { dw1s[tid] = dw1[tid]; db0s[tid] = db0[tid]; }
    if (tid == 0) sm[F_DB1] = db1[0];
    if (tid < ROWS) {
        xps[tid] = 0.0f;
        out[(u64)(row0 + tid)*50] = 0.0f;
    }

    // ---- encoder (scalar fp32) ----
    {
        const int p = tid & 15, t = tid >> 4;
        float acc[4][4];
        #pragma unroll
        for (int uu = 0; uu < 4; ++uu)
            #pragma unroll
            for (int m = 0; m < 4; ++m) acc[uu][m] = 0.0f;
        const float4* x4  = (const float4*)x;
        const float4* w04 = (const float4*)ew0;
        for (int k4 = 0; k4 < 64; ++k4) {
            float xa[4][4];
            #pragma unroll
            for (int m = 0; m < 4; ++m) {
                float4 v = __ldg(&x4[(u64)(row0 + p + 16*m)*64 + k4]);
                xa[m][0] = v.x; xa[m][1] = v.y; xa[m][2] = v.z; xa[m][3] = v.w;
            }
            #pragma unroll
            for (int kk = 0; kk < 4; ++kk) {
                float4 wv = __ldg(&w04[(k4*4 + kk)*32 + t]);
                #pragma unroll
                for (int m = 0; m < 4; ++m) {
                    acc[0][m] = fmaf(wv.x, xa[m][kk], acc[0][m]);
                    acc[1][m] = fmaf(wv.y, xa[m][kk], acc[1][m]);
                    acc[2][m] = fmaf(wv.z, xa[m][kk], acc[2][m]);
                    acc[3][m] = fmaf(wv.w, xa[m][kk], acc[3][m]);
                }
            }
        }
        __syncthreads();
        #pragma unroll
        for (int uu = 0; uu < 4; ++uu) {
            int u = t*4 + uu;
            float bv = __ldg(&eb0[u]);
            #pragma unroll
            for (int m = 0; m < 4; ++m)
                ha[(p + 16*m)*HPAD + u] = fmaxf(acc[uu][m] + bv, 0.0f);
        }
        __syncthreads();
        enc_layer128(ew1, eb1, ha, p, t, true);
        enc_layer128(ew2, eb2, ha, p, t, false);
    }

    const int wm = wid & 7;        // unit block (16 units, all 3 gates)
    const int wn = wid >> 3;       // row half (32 rows)

    // ---- h0: ha -> bf16 hi/lo tiles + hold slots ----
    for (int j = tid; j < 8192; j += NTHR) {
        int r = j >> 7, u = j & 127;
        float v = ha[r*HPAD + u];
        __nv_bfloat16 bh = __float2bfloat16(v);
        __nv_bfloat16 bl = __float2bfloat16(v - __bfloat162float(bh));
        *(__nv_bfloat16*)(hhi + r*272 + u*2) = bh;
        *(__nv_bfloat16*)(hlo + r*272 + u*2) = bl;
    }
    #pragma unroll
    for (int i = 0; i < 2; ++i)
        #pragma unroll
        for (int nt = 0; nt < 4; ++nt)
            #pragma unroll
            for (int j = 0; j < 2; ++j) {
                int u = wm*16 + (lane >> 2) + 8*i;
                int r = wn*32 + nt*8 + (lane & 3)*2 + j;
                hs[(i*8 + nt*2 + j)*512 + tid] = ha[r*HPAD + u];
            }
    __syncthreads();
    const float db1v = sm[F_DB1];

    // ---- GRU + decoder, 49 steps ----
    const uint4* wf = g_wfrag;

    for (int s = 0; s < NSTEP; ++s) {
        float acc[3][4][4];
        #pragma unroll
        for (int g = 0; g < 3; ++g)
            #pragma unroll
            for (int nt = 0; nt < 4; ++nt)
                #pragma unroll
                for (int q = 0; q < 4; ++q) acc[g][nt][q] = 0.0f;

        #pragma unroll 2
        for (int k = 0; k < 8; ++k) {
            u32 bh[4][2], bl[4][2];
            #pragma unroll
            for (int nt = 0; nt < 4; ++nt) {
                int r = wn*32 + nt*8 + (lane >> 2);
                int off = r*272 + k*32 + (lane & 3)*4;
                bh[nt][0] = *(const u32*)(hhi + off);
                bh[nt][1] = *(const u32*)(hhi + off + 16);
                bl[nt][0] = *(const u32*)(hlo + off);
                bl[nt][1] = *(const u32*)(hlo + off + 16);
            }
            #pragma unroll
            for (int g = 0; g < 3; ++g) {
                uint4 ah = __ldg(&wf[(g*8 + wm)*256 + k*32 + lane]);
                uint4 al = __ldg(&wf[6144 + (g*8 + wm)*256 + k*32 + lane]);
                #pragma unroll
                for (int nt = 0; nt < 4; ++nt) {
                    MMA(acc[g][nt], ah, bh[nt][0], bh[nt][1]);
                    MMA(acc[g][nt], ah, bl[nt][0], bl[nt][1]);
                    MMA(acc[g][nt], al, bh[nt][0], bh[nt][1]);
                }
            }
        }

        __syncthreads();   // all mma reads of h tiles complete

        // ---- epilogue: gates -> new h, write tiles + hold slots ----
        #pragma unroll
        for (int i = 0; i < 2; ++i) {
            int u = wm*16 + (lane >> 2) + 8*i;
            float wir = wihs[u], wiz = wihs[128 + u], win = wihs[256 + u];
            float br  = bihs[u]       + bhhs[u];
            float bz  = bihs[128 + u] + bhhs[128 + u];
            float bni = bihs[256 + u];
            float bnh = bhhs[256 + u];
            #pragma unroll
            for (int nt = 0; nt < 4; ++nt) {
                #pragma unroll
                for (int j = 0; j < 2; ++j) {
                    int r = wn*32 + nt*8 + (lane & 3)*2 + j;
                    int q = 2*i + j;
                    int hidx = (i*8 + nt*2 + j)*512 + tid;
                    float xp   = xps[r];
                    float hold = hs[hidx];
                    float rg = sigm(acc[0][nt][q] + fmaf(xp, wir, br));
                    float zg = sigm(acc[1][nt][q] + fmaf(xp, wiz, bz));
                    float ng = tanh_f(fmaf(xp, win, bni) + rg*(acc[2][nt][q] + bnh));
                    float h  = (1.0f - zg)*ng + zg*hold;
                    hs[hidx] = h;
                    __nv_bfloat16 bhv = __float2bfloat16(h);
                    __nv_bfloat16 blv = __float2bfloat16(h - __bfloat162float(bhv));
                    *(__nv_bfloat16*)(hhi + r*272 + u*2) = bhv;
                    *(__nv_bfloat16*)(hlo + r*272 + u*2) = blv;
                }
            }
        }
        __syncthreads();   // new tiles visible

        // ---- decoder via MMA (warps 0..7, one 8-row tile each) ----
        if (wid < 8) {
            float dacc[4] = {0.0f, 0.0f, 0.0f, 0.0f};
            #pragma unroll
            for (int k = 0; k < 8; ++k) {
                int r = wid*8 + (lane >> 2);
                int off = r*272 + k*32 + (lane & 3)*4;
                u32 b0 = *(const u32*)(hhi + off);
                u32 b1 = *(const u32*)(hhi + off + 16);
                u32 c0 = *(const u32*)(hlo + off);
                u32 c1 = *(const u32*)(hlo + off + 16);
                uint4 ah = __ldg(&g_dfrag[k*32 + lane]);
                uint4 al = __ldg(&g_dfrag[256 + k*32 + lane]);
                MMA(dacc, ah, b0, b1);
                MMA(dacc, ah, c0, c1);
                MMA(dacc, al, b0, b1);
            }
            int i = lane >> 2;
            float w1a = dw1s[i], w1b = dw1s[i + 8];
            float b0a = db0s[i], b0b = db0s[i + 8];
            float v0 = fmaxf(dacc[0] + b0a, 0.0f)*w1a + fmaxf(dacc[2] + b0b, 0.0f)*w1b;
            float v1 = fmaxf(dacc[1] + b0a, 0.0f)*w1a + fmaxf(dacc[3] + b0b, 0.0f)*w1b;
            v0 += __shfl_xor_sync(0xffffffffu, v0, 4);
            v0 += __shfl_xor_sync(0xffffffffu, v0, 8);
            v0 += __shfl_xor_sync(0xffffffffu, v0, 16);
            v1 += __shfl_xor_sync(0xffffffffu, v1, 4);
            v1 += __shfl_xor_sync(0xffffffffu, v1, 8);
            v1 += __shfl_xor_sync(0xffffffffu, v1, 16);
            if (lane < 4) {
                int r0 = wid*8 + lane*2;
                float o0 = v0 + db1v;
                float o1 = v1 + db1v;
                out[(u64)(row0 + r0)*50 + s + 1] = o0;
                out[(u64)(row0 + r0 + 1)*50 + s + 1] = o1;
                xps[r0]     = o0;
                xps[r0 + 1] = o1;
            }
        }
        __syncthreads();   // xps visible; tiles stable for next step
    }
}

extern "C" void kernel_launch(void* const* d_in, const int* in_sizes, int n_in,
                              void* d_out, int out_size) {
    (void)in_sizes; (void)n_in; (void)out_size;
    const float* x   = (const float*)d_in[0];
    const float* ew0 = (const float*)d_in[1];
    const float* eb0 = (const float*)d_in[2];
    const float* ew1 = (const float*)d_in[3];
    const float* eb1 = (const float*)d_in[4];
    const float* ew2 = (const float*)d_in[5];
    const float* eb2 = (const float*)d_in[6];
    const float* wih = (const float*)d_in[7];
    const float* whh = (const float*)d_in[8];
    const float* bih = (const float*)d_in[9];
    const float* bhh = (const float*)d_in[10];
    const float* dw0 = (const float*)d_in[11];
    const float* db0 = (const float*)d_in[12];
    const float* dw1 = (const float*)d_in[13];
    const float* db1 = (const float*)d_in[14];
    float* out = (float*)d_out;

    cudaFuncSetAttribute(gru_kernel, cudaFuncAttributeMaxDynamicSharedMemorySize, SMEM_BYTES);

    repack<<<25, 512>>>(whh, dw0);
    gru_kernel<<<NBLK, NTHR, SMEM_BYTES>>>(x, ew0, eb0, ew1, eb1, ew2, eb2,
                                           wih, whh, bih, bhh, dw0, db0, dw1, db1, out);
}

// round 8
// speedup vs baseline: 2.9970x; 1.0331x over previous
#include <cuda_runtime.h>
#include <cuda_bf16.h>

typedef unsigned int u32;
typedef unsigned long long u64;

#define NBLK  128
#define NTHR  512
#define ROWS  64
#define HPAD  132
#define NSTEP 49

// ---- dynamic smem layout (float offsets) ----
#define F_XPS   0        // 64
#define F_WIHS  64       // 384
#define F_BIHS  448      // 384
#define F_BHHS  832      // 384
#define F_DW1   1216     // 16
#define F_DB0   1232     // 16
#define F_DB1   1248     // 1 (pad to 1280)
#define F_HHI   1280     // bf16 [64][136] = 4352 floats
#define F_HLO   5632     // 4352
#define F_HS    9984     // 16*512 per-thread hold slots
#define F_HA    18176    // 64*132 encoder scratch
#define SMEM_FLOATS 26624
#define SMEM_BYTES  (SMEM_FLOATS*4)

// GRU A fragments: [prec][g][wm][k][lane] as uint4
__device__ uint4 g_wfrag[2 * 3 * 8 * 8 * 32];
// decoder A fragments: [prec][k][lane] as uint4 (m16 x k128)
__device__ uint4 g_dfrag[2 * 8 * 32];

#define MMA(c, a, b0v, b1v) asm volatile( \
    "mma.sync.aligned.m16n8k16.row.col.f32.bf16.bf16.f32 " \
    "{%0,%1,%2,%3}, {%4,%5,%6,%7}, {%8,%9}, {%0,%1,%2,%3};" \
    : "+f"((c)[0]), "+f"((c)[1]), "+f"((c)[2]), "+f"((c)[3]) \
    : "r"((a).x), "r"((a).y), "r"((a).z), "r"((a).w), "r"(b0v), "r"(b1v))

__device__ __forceinline__ float sigm(float x) {
    return __fdividef(1.0f, 1.0f + __expf(-x));
}
__device__ __forceinline__ float tanh_f(float x) {
    float ax = fabsf(x);
    float e  = __expf(-2.0f * ax);
    float r  = __fdividef(1.0f - e, 1.0f + e);
    return copysignf(r, x);
}
__device__ __forceinline__ u32 pack_bf2(__nv_bfloat16 lo, __nv_bfloat16 hi) {
    return ((u32)__bfloat16_as_ushort(hi) << 16) | (u32)__bfloat16_as_ushort(lo);
}

// ---------------- weight repack ----------------
__global__ void repack(const float* __restrict__ whh, const float* __restrict__ dw0) {
    int idx = blockIdx.x * blockDim.x + threadIdx.x;
    if (idx < 12288) {
        int lane = idx & 31;
        int k    = (idx >> 5) & 7;
        int wm   = (idx >> 8) & 7;
        int gp   = idx >> 11;          // 0..5
        int g    = gp % 3;
        int prec = gp / 3;
        int row  = g * 128 + wm * 16 + (lane >> 2);
        int k0   = k * 16 + (lane & 3) * 2;
        u32 o[4];
        #pragma unroll
        for (int q = 0; q < 4; ++q) {
            int rr = row + 8 * (q & 1);
            int kk = k0 + 8 * (q >> 1);
            float v0 = whh[rr * 128 + kk];
            float v1 = whh[rr * 128 + kk + 1];
            __nv_bfloat16 h0 = __float2bfloat16(v0);
            __nv_bfloat16 h1 = __float2bfloat16(v1);
            if (prec == 0) o[q] = pack_bf2(h0, h1);
            else o[q] = pack_bf2(__float2bfloat16(v0 - __bfloat162float(h0)),
                                 __float2bfloat16(v1 - __bfloat162float(h1)));
        }
        g_wfrag[idx] = make_uint4(o[0], o[1], o[2], o[3]);
    } else if (idx < 12800) {
        int local = idx - 12288;
        int lane = local & 31;
        int k    = (local >> 5) & 7;
        int prec = local >> 8;
        int row  = lane >> 2;
        int k0   = k * 16 + (lane & 3) * 2;
        u32 o[4];
        #pragma unroll
        for (int q = 0; q < 4; ++q) {
            int rr = row + 8 * (q & 1);
            int kk = k0 + 8 * (q >> 1);
            float v0 = dw0[kk * 16 + rr];
            float v1 = dw0[(kk + 1) * 16 + rr];
            __nv_bfloat16 h0 = __float2bfloat16(v0);
            __nv_bfloat16 h1 = __float2bfloat16(v1);
            if (prec == 0) o[q] = pack_bf2(h0, h1);
            else o[q] = pack_bf2(__float2bfloat16(v0 - __bfloat162float(h0)),
                                 __float2bfloat16(v1 - __bfloat162float(h1)));
        }
        g_dfrag[local] = make_uint4(o[0], o[1], o[2], o[3]);
    }
}

// one 128->128 encoder layer (reads/writes ha), scalar fp32
__device__ __forceinline__ void enc_layer128(const float* __restrict__ w,
                                             const float* __restrict__ b,
                                             float* ha, int p, int t, bool relu_on) {
    float acc[4][4];
    #pragma unroll
    for (int uu = 0; uu < 4; ++uu)
        #pragma unroll
        for (int m = 0; m < 4; ++m) acc[uu][m] = 0.0f;
    const float4* w4 = (const float4*)w;
    for (int k4 = 0; k4 < 32; ++k4) {
        float xa[4][4];
        #pragma unroll
        for (int m = 0; m < 4; ++m) {
            float4 v = *(const float4*)&ha[(p + 16*m)*HPAD + k4*4];
            xa[m][0] = v.x; xa[m][1] = v.y; xa[m][2] = v.z; xa[m][3] = v.w;
        }
        #pragma unroll
        for (int kk = 0; kk < 4; ++kk) {
            float4 wv = __ldg(&w4[(k4*4 + kk)*32 + t]);
            #pragma unroll
            for (int m = 0; m < 4; ++m) {
                acc[0][m] = fmaf(wv.x, xa[m][kk], acc[0][m]);
                acc[1][m] = fmaf(wv.y, xa[m][kk], acc[1][m]);
                acc[2][m] = fmaf(wv.z, xa[m][kk], acc[2][m]);
                acc[3][m] = fmaf(wv.w, xa[m][kk], acc[3][m]);
            }
        }
    }
    __syncthreads();
    #pragma unroll
    for (int uu = 0; uu < 4; ++uu) {
        int u = t*4 + uu;
        float bv = __ldg(&b[u]);
        #pragma unroll
        for (int m = 0; m < 4; ++m) {
            float v = acc[uu][m] + bv;
            ha[(p + 16*m)*HPAD + u] = relu_on ? fmaxf(v, 0.0f) : v;
        }
    }
    __syncthreads();
}

__global__ void __launch_bounds__(NTHR, 1)
gru_kernel(const float* __restrict__ x,
           const float* __restrict__ ew0, const float* __restrict__ eb0,
           const float* __restrict__ ew1, const float* __restrict__ eb1,
           const float* __restrict__ ew2, const float* __restrict__ eb2,
           const float* __restrict__ wih, const float* __restrict__ whh,
           const float* __restrict__ bih, const float* __restrict__ bhh,
           const float* __restrict__ dw0, const float* __restrict__ db0,
           const float* __restrict__ dw1, const float* __restrict__ db1,
           float* __restrict__ out) {
    extern __shared__ float sm[];
    float* xps  = sm + F_XPS;
    float* wihs = sm + F_WIHS;
    float* bihs = sm + F_BIHS;
    float* bhhs = sm + F_BHHS;
    float* dw1s = sm + F_DW1;
    float* db0s = sm + F_DB0;
    char*  hhi  = (char*)(sm + F_HHI);   // bf16 [r][136]
    char*  hlo  = (char*)(sm + F_HLO);
    float* hs   = sm + F_HS;             // hold slots [16][512]
    float* ha   = sm + F_HA;

    const int tid  = threadIdx.x;
    const int wid  = tid >> 5;
    const int lane = tid & 31;
    const int row0 = blockIdx.x * ROWS;

    // ---- small smem init ----
    for (int j = tid; j < 384; j += NTHR) {
        wihs[j] = wih[j]; bihs[j] = bih[j]; bhhs[j] = bhh[j];
    }
    if (tid < 16) { dw1s[tid] = dw1[tid]; db0s[tid] = db0[tid]; }
    if (tid == 0) sm[F_DB1] = db1[0];
    if (tid < ROWS) {
        xps[tid] = 0.0f;
        out[(u64)(row0 + tid)*50] = 0.0f;
    }

    // ---- encoder (scalar fp32) ----
    {
        const int p = tid & 15, t = tid >> 4;
        float acc[4][4];
        #pragma unroll
        for (int uu = 0; uu < 4; ++uu)
            #pragma unroll
            for (int m = 0; m < 4; ++m) acc[uu][m] = 0.0f;
        const float4* x4  = (const float4*)x;
        const float4* w04 = (const float4*)ew0;
        for (int k4 = 0; k4 < 64; ++k4) {
            float xa[4][4];
            #pragma unroll
            for (int m = 0; m < 4; ++m) {
                float4 v = __ldg(&x4[(u64)(row0 + p + 16*m)*64 + k4]);
                xa[m][0] = v.x; xa[m][1] = v.y; xa[m][2] = v.z; xa[m][3] = v.w;
            }
            #pragma unroll
            for (int kk = 0; kk < 4; ++kk) {
                float4 wv = __ldg(&w04[(k4*4 + kk)*32 + t]);
                #pragma unroll
                for (int m = 0; m < 4; ++m) {
                    acc[0][m] = fmaf(wv.x, xa[m][kk], acc[0][m]);
                    acc[1][m] = fmaf(wv.y, xa[m][kk], acc[1][m]);
                    acc[2][m] = fmaf(wv.z, xa[m][kk], acc[2][m]);
                    acc[3][m] = fmaf(wv.w, xa[m][kk], acc[3][m]);
                }
            }
        }
        __syncthreads();
        #pragma unroll
        for (int uu = 0; uu < 4; ++uu) {
            int u = t*4 + uu;
            float bv = __ldg(&eb0[u]);
            #pragma unroll
            for (int m = 0; m < 4; ++m)
                ha[(p + 16*m)*HPAD + u] = fmaxf(acc[uu][m] + bv, 0.0f);
        }
        __syncthreads();
        enc_layer128(ew1, eb1, ha, p, t, true);
        enc_layer128(ew2, eb2, ha, p, t, false);
    }

    const int wm = wid & 7;        // unit block (16 units, all 3 gates)
    const int wn = wid >> 3;       // row half (32 rows)

    // ---- h0: ha -> bf16 hi/lo tiles + hold slots ----
    for (int j = tid; j < 8192; j += NTHR) {
        int r = j >> 7, u = j & 127;
        float v = ha[r*HPAD + u];
        __nv_bfloat16 bh = __float2bfloat16(v);
        __nv_bfloat16 bl = __float2bfloat16(v - __bfloat162float(bh));
        *(__nv_bfloat16*)(hhi + r*272 + u*2) = bh;
        *(__nv_bfloat16*)(hlo + r*272 + u*2) = bl;
    }
    #pragma unroll
    for (int i = 0; i < 2; ++i)
        #pragma unroll
        for (int nt = 0; nt < 4; ++nt)
            #pragma unroll
            for (int j = 0; j < 2; ++j) {
                int u = wm*16 + (lane >> 2) + 8*i;
                int r = wn*32 + nt*8 + (lane & 3)*2 + j;
                hs[(i*8 + nt*2 + j)*512 + tid] = ha[r*HPAD + u];
            }
    __syncthreads();
    const float db1v = sm[F_DB1];

    // decoder (warps 8..15 only): reads current tiles, writes out col + xps
    auto decoder = [&](int col) {
        int dwid = wid - 8;
        float dacc[4] = {0.0f, 0.0f, 0.0f, 0.0f};
        #pragma unroll
        for (int k = 0; k < 8; ++k) {
            int r = dwid*8 + (lane >> 2);
            int off = r*272 + k*32 + (lane & 3)*4;
            u32 b0 = *(const u32*)(hhi + off);
            u32 b1 = *(const u32*)(hhi + off + 16);
            u32 c0 = *(const u32*)(hlo + off);
            u32 c1 = *(const u32*)(hlo + off + 16);
            uint4 ah = __ldg(&g_dfrag[k*32 + lane]);
            uint4 al = __ldg(&g_dfrag[256 + k*32 + lane]);
            MMA(dacc, ah, b0, b1);
            MMA(dacc, ah, c0, c1);
            MMA(dacc, al, b0, b1);
        }
        int i = lane >> 2;
        float w1a = dw1s[i], w1b = dw1s[i + 8];
        float b0a = db0s[i], b0b = db0s[i + 8];
        float v0 = fmaxf(dacc[0] + b0a, 0.0f)*w1a + fmaxf(dacc[2] + b0b, 0.0f)*w1b;
        float v1 = fmaxf(dacc[1] + b0a, 0.0f)*w1a + fmaxf(dacc[3] + b0b, 0.0f)*w1b;
        v0 += __shfl_xor_sync(0xffffffffu, v0, 4);
        v0 += __shfl_xor_sync(0xffffffffu, v0, 8);
        v0 += __shfl_xor_sync(0xffffffffu, v0, 16);
        v1 += __shfl_xor_sync(0xffffffffu, v1, 4);
        v1 += __shfl_xor_sync(0xffffffffu, v1, 8);
        v1 += __shfl_xor_sync(0xffffffffu, v1, 16);
        if (lane < 4) {
            int r0 = dwid*8 + lane*2;
            float o0 = v0 + db1v;
            float o1 = v1 + db1v;
            out[(u64)(row0 + r0)*50 + col] = o0;
            out[(u64)(row0 + r0 + 1)*50 + col] = o1;
            xps[r0]     = o0;
            xps[r0 + 1] = o1;
        }
    };

    // ---- GRU (+fused decoder), 49 steps, 2 syncs/step ----
    const uint4* wf = g_wfrag;

    for (int s = 0; s < NSTEP; ++s) {
        // ---- phase A: decoder (warps 8-15, tiles = h_s, s>=1) + GRU MMA (all) ----
        if (wid >= 8 && s > 0) decoder(s);

        float acc[3][4][4];
        #pragma unroll
        for (int g = 0; g < 3; ++g)
            #pragma unroll
            for (int nt = 0; nt < 4; ++nt)
                #pragma unroll
                for (int q = 0; q < 4; ++q) acc[g][nt][q] = 0.0f;

        #pragma unroll 2
        for (int k = 0; k < 8; ++k) {
            u32 bh[4][2], bl[4][2];
            #pragma unroll
            for (int nt = 0; nt < 4; ++nt) {
                int r = wn*32 + nt*8 + (lane >> 2);
                int off = r*272 + k*32 + (lane & 3)*4;
                bh[nt][0] = *(const u32*)(hhi + off);
                bh[nt][1] = *(const u32*)(hhi + off + 16);
                bl[nt][0] = *(const u32*)(hlo + off);
                bl[nt][1] = *(const u32*)(hlo + off + 16);
            }
            #pragma unroll
            for (int g = 0; g < 3; ++g) {
                uint4 ah = __ldg(&wf[(g*8 + wm)*256 + k*32 + lane]);
                uint4 al = __ldg(&wf[6144 + (g*8 + wm)*256 + k*32 + lane]);
                #pragma unroll
                for (int nt = 0; nt < 4; ++nt) {
                    MMA(acc[g][nt], ah, bh[nt][0], bh[nt][1]);
                    MMA(acc[g][nt], ah, bl[nt][0], bl[nt][1]);
                    MMA(acc[g][nt], al, bh[nt][0], bh[nt][1]);
                }
            }
        }

        __syncthreads();   // tile reads done (MMA + decoder), xps written

        // ---- phase B: epilogue -> h_{s+1}, write tiles + hold slots ----
        #pragma unroll
        for (int i = 0; i < 2; ++i) {
            int u = wm*16 + (lane >> 2) + 8*i;
            float wir = wihs[u], wiz = wihs[128 + u], win = wihs[256 + u];
            float br  = bihs[u]       + bhhs[u];
            float bz  = bihs[128 + u] + bhhs[128 + u];
            float bni = bihs[256 + u];
            float bnh = bhhs[256 + u];
            #pragma unroll
            for (int nt = 0; nt < 4; ++nt) {
                #pragma unroll
                for (int j = 0; j < 2; ++j) {
                    int r = wn*32 + nt*8 + (lane & 3)*2 + j;
                    int q = 2*i + j;
                    int hidx = (i*8 + nt*2 + j)*512 + tid;
                    float xp   = xps[r];
                    float hold = hs[hidx];
                    float rg = sigm(acc[0][nt][q] + fmaf(xp, wir, br));
                    float zg = sigm(acc[1][nt][q] + fmaf(xp, wiz, bz));
                    float ng = tanh_f(fmaf(xp, win, bni) + rg*(acc[2][nt][q] + bnh));
                    float h  = (1.0f - zg)*ng + zg*hold;
                    hs[hidx] = h;
                    __nv_bfloat16 bhv = __float2bfloat16(h);
                    __nv_bfloat16 blv = __float2bfloat16(h - __bfloat162float(bhv));
                    *(__nv_bfloat16*)(hhi + r*272 + u*2) = bhv;
                    *(__nv_bfloat16*)(hlo + r*272 + u*2) = blv;
                }
            }
        }
        __syncthreads();   // new tiles visible
    }

    // final decoder: tiles = h_49 -> out col 49
    if (wid >= 8) decoder(NSTEP);
}

extern "C" void kernel_launch(void* const* d_in, const int* in_sizes, int n_in,
                              void* d_out, int out_size) {
    (void)in_sizes; (void)n_in; (void)out_size;
    const float* x   = (const float*)d_in[0];
    const float* ew0 = (const float*)d_in[1];
    const float* eb0 = (const float*)d_in[2];
    const float* ew1 = (const float*)d_in[3];
    const float* eb1 = (const float*)d_in[4];
    const float* ew2 = (const float*)d_in[5];
    const float* eb2 = (const float*)d_in[6];
    const float* wih = (const float*)d_in[7];
    const float* whh = (const float*)d_in[8];
    const float* bih = (const float*)d_in[9];
    const float* bhh = (const float*)d_in[10];
    const float* dw0 = (const float*)d_in[11];
    const float* db0 = (const float*)d_in[12];
    const float* dw1 = (const float*)d_in[13];
    const float* db1 = (const float*)d_in[14];
    float* out = (float*)d_out;

    cudaFuncSetAttribute(gru_kernel, cudaFuncAttributeMaxDynamicSharedMemorySize, SMEM_BYTES);

    repack<<<25, 512>>>(whh, dw0);
    gru_kernel<<<NBLK, NTHR, SMEM_BYTES>>>(x, ew0, eb0, ew1, eb1, ew2, eb2,
                                           wih, whh, bih, bhh, dw0, db0, dw1, db1, out);
}

// round 9
// speedup vs baseline: 3.3381x; 1.1138x over previous
#include <cuda_runtime.h>
#include <cuda_bf16.h>

typedef unsigned int u32;
typedef unsigned long long u64;

#define NBLK  128
#define NTHR  512
#define ROWS  64
#define HPAD  132
#define NSTEP 49

// ---- dynamic smem layout (float offsets) ----
#define F_XPS   0        // 64
#define F_WIHS  64       // 384
#define F_BIHS  448      // 384
#define F_BHHS  832      // 384
#define F_DW1   1216     // 16
#define F_DB0   1232     // 16
#define F_DB1   1248     // 1 (pad to 1280)
#define F_HHI   1280     // bf16 [64][136] = 4352 floats
#define F_HLO   5632     // 4352
#define F_HS    9984     // 16*512 per-thread hold slots
#define F_HA    18176    // 64*132 encoder scratch
#define SMEM_FLOATS 26624
#define SMEM_BYTES  (SMEM_FLOATS*4)

// GRU A fragments: [prec][g][wm][k][lane] as uint4
__device__ uint4 g_wfrag[2 * 3 * 8 * 8 * 32];
// decoder A fragments: [prec][k][lane] as uint4 (m16 x k128)
__device__ uint4 g_dfrag[2 * 8 * 32];

#define MMA(c, a, b0v, b1v) asm volatile( \
    "mma.sync.aligned.m16n8k16.row.col.f32.bf16.bf16.f32 " \
    "{%0,%1,%2,%3}, {%4,%5,%6,%7}, {%8,%9}, {%0,%1,%2,%3};" \
    : "+f"((c)[0]), "+f"((c)[1]), "+f"((c)[2]), "+f"((c)[3]) \
    : "r"((a).x), "r"((a).y), "r"((a).z), "r"((a).w), "r"(b0v), "r"(b1v))

#define BARG(gid) asm volatile("bar.sync %0, %1;" :: "r"((gid) + 1), "r"(256) : "memory")

__device__ __forceinline__ float tanha(float x) {
    float y;
    asm("tanh.approx.f32 %0, %1;" : "=f"(y) : "f"(x));
    return y;
}
__device__ __forceinline__ float sigm(float x) {
    return fmaf(0.5f, tanha(0.5f * x), 0.5f);
}
__device__ __forceinline__ u32 pack_bf2(__nv_bfloat16 lo, __nv_bfloat16 hi) {
    return ((u32)__bfloat16_as_ushort(hi) << 16) | (u32)__bfloat16_as_ushort(lo);
}

// ---------------- weight repack ----------------
__global__ void repack(const float* __restrict__ whh, const float* __restrict__ dw0) {
    int idx = blockIdx.x * blockDim.x + threadIdx.x;
    if (idx < 12288) {
        int lane = idx & 31;
        int k    = (idx >> 5) & 7;
        int wm   = (idx >> 8) & 7;
        int gp   = idx >> 11;          // 0..5
        int g    = gp % 3;
        int prec = gp / 3;
        int row  = g * 128 + wm * 16 + (lane >> 2);
        int k0   = k * 16 + (lane & 3) * 2;
        u32 o[4];
        #pragma unroll
        for (int q = 0; q < 4; ++q) {
            int rr = row + 8 * (q & 1);
            int kk = k0 + 8 * (q >> 1);
            float v0 = whh[rr * 128 + kk];
            float v1 = whh[rr * 128 + kk + 1];
            __nv_bfloat16 h0 = __float2bfloat16(v0);
            __nv_bfloat16 h1 = __float2bfloat16(v1);
            if (prec == 0) o[q] = pack_bf2(h0, h1);
            else o[q] = pack_bf2(__float2bfloat16(v0 - __bfloat162float(h0)),
                                 __float2bfloat16(v1 - __bfloat162float(h1)));
        }
        g_wfrag[idx] = make_uint4(o[0], o[1], o[2], o[3]);
    } else if (idx < 12800) {
        int local = idx - 12288;
        int lane = local & 31;
        int k    = (local >> 5) & 7;
        int prec = local >> 8;
        int row  = lane >> 2;
        int k0   = k * 16 + (lane & 3) * 2;
        u32 o[4];
        #pragma unroll
        for (int q = 0; q < 4; ++q) {
            int rr = row + 8 * (q & 1);
            int kk = k0 + 8 * (q >> 1);
            float v0 = dw0[kk * 16 + rr];
            float v1 = dw0[(kk + 1) * 16 + rr];
            __nv_bfloat16 h0 = __float2bfloat16(v0);
            __nv_bfloat16 h1 = __float2bfloat16(v1);
            if (prec == 0) o[q] = pack_bf2(h0, h1);
            else o[q] = pack_bf2(__float2bfloat16(v0 - __bfloat162float(h0)),
                                 __float2bfloat16(v1 - __bfloat162float(h1)));
        }
        g_dfrag[local] = make_uint4(o[0], o[1], o[2], o[3]);
    }
}

// one 128->128 encoder layer (reads/writes ha), scalar fp32
__device__ __forceinline__ void enc_layer128(const float* __restrict__ w,
                                             const float* __restrict__ b,
                                             float* ha, int p, int t, bool relu_on) {
    float acc[4][4];
    #pragma unroll
    for (int uu = 0; uu < 4; ++uu)
        #pragma unroll
        for (int m = 0; m < 4; ++m) acc[uu][m] = 0.0f;
    const float4* w4 = (const float4*)w;
    for (int k4 = 0; k4 < 32; ++k4) {
        float xa[4][4];
        #pragma unroll
        for (int m = 0; m < 4; ++m) {
            float4 v = *(const float4*)&ha[(p + 16*m)*HPAD + k4*4];
            xa[m][0] = v.x; xa[m][1] = v.y; xa[m][2] = v.z; xa[m][3] = v.w;
        }
        #pragma unroll
        for (int kk = 0; kk < 4; ++kk) {
            float4 wv = __ldg(&w4[(k4*4 + kk)*32 + t]);
            #pragma unroll
            for (int m = 0; m < 4; ++m) {
                acc[0][m] = fmaf(wv.x, xa[m][kk], acc[0][m]);
                acc[1][m] = fmaf(wv.y, xa[m][kk], acc[1][m]);
                acc[2][m] = fmaf(wv.z, xa[m][kk], acc[2][m]);
                acc[3][m] = fmaf(wv.w, xa[m][kk], acc[3][m]);
            }
        }
    }
    __syncthreads();
    #pragma unroll
    for (int uu = 0; uu < 4; ++uu) {
        int u = t*4 + uu;
        float bv = __ldg(&b[u]);
        #pragma unroll
        for (int m = 0; m < 4; ++m) {
            float v = acc[uu][m] + bv;
            ha[(p + 16*m)*HPAD + u] = relu_on ? fmaxf(v, 0.0f) : v;
        }
    }
    __syncthreads();
}

__global__ void __launch_bounds__(NTHR, 1)
gru_kernel(const float* __restrict__ x,
           const float* __restrict__ ew0, const float* __restrict__ eb0,
           const float* __restrict__ ew1, const float* __restrict__ eb1,
           const float* __restrict__ ew2, const float* __restrict__ eb2,
           const float* __restrict__ wih, const float* __restrict__ whh,
           const float* __restrict__ bih, const float* __restrict__ bhh,
           const float* __restrict__ dw0, const float* __restrict__ db0,
           const float* __restrict__ dw1, const float* __restrict__ db1,
           float* __restrict__ out) {
    extern __shared__ float sm[];
    float* xps  = sm + F_XPS;
    float* wihs = sm + F_WIHS;
    float* bihs = sm + F_BIHS;
    float* bhhs = sm + F_BHHS;
    float* dw1s = sm + F_DW1;
    float* db0s = sm + F_DB0;
    char*  hhi  = (char*)(sm + F_HHI);   // bf16 [r][136]
    char*  hlo  = (char*)(sm + F_HLO);
    float* hs   = sm + F_HS;             // hold slots [16][512]
    float* ha   = sm + F_HA;

    const int tid  = threadIdx.x;
    const int wid  = tid >> 5;
    const int lane = tid & 31;
    const int row0 = blockIdx.x * ROWS;

    // ---- small smem init ----
    for (int j = tid; j < 384; j += NTHR) {
        wihs[j] = wih[j]; bihs[j] = bih[j]; bhhs[j] = bhh[j];
    }
    if (tid < 16) { dw1s[tid] = dw1[tid]; db0s[tid] = db0[tid]; }
    if (tid == 0) sm[F_DB1] = db1[0];
    if (tid < ROWS) {
        xps[tid] = 0.0f;
        out[(u64)(row0 + tid)*50] = 0.0f;
    }

    // ---- encoder (scalar fp32) ----
    {
        const int p = tid & 15, t = tid >> 4;
        float acc[4][4];
        #pragma unroll
        for (int uu = 0; uu < 4; ++uu)
            #pragma unroll
            for (int m = 0; m < 4; ++m) acc[uu][m] = 0.0f;
        const float4* x4  = (const float4*)x;
        const float4* w04 = (const float4*)ew0;
        for (int k4 = 0; k4 < 64; ++k4) {
            float xa[4][4];
            #pragma unroll
            for (int m = 0; m < 4; ++m) {
                float4 v = __ldg(&x4[(u64)(row0 + p + 16*m)*64 + k4]);
                xa[m][0] = v.x; xa[m][1] = v.y; xa[m][2] = v.z; xa[m][3] = v.w;
            }
            #pragma unroll
            for (int kk = 0; kk < 4; ++kk) {
                float4 wv = __ldg(&w04[(k4*4 + kk)*32 + t]);
                #pragma unroll
                for (int m = 0; m < 4; ++m) {
                    acc[0][m] = fmaf(wv.x, xa[m][kk], acc[0][m]);
                    acc[1][m] = fmaf(wv.y, xa[m][kk], acc[1][m]);
                    acc[2][m] = fmaf(wv.z, xa[m][kk], acc[2][m]);
                    acc[3][m] = fmaf(wv.w, xa[m][kk], acc[3][m]);
                }
            }
        }
        __syncthreads();
        #pragma unroll
        for (int uu = 0; uu < 4; ++uu) {
            int u = t*4 + uu;
            float bv = __ldg(&eb0[u]);
            #pragma unroll
            for (int m = 0; m < 4; ++m)
                ha[(p + 16*m)*HPAD + u] = fmaxf(acc[uu][m] + bv, 0.0f);
        }
        __syncthreads();
        enc_layer128(ew1, eb1, ha, p, t, true);
        enc_layer128(ew2, eb2, ha, p, t, false);
    }

    const int grp   = wid >> 3;     // row group: rows [grp*32, grp*32+32)
    const int wm    = wid & 7;      // unit block (16 units, all 3 gates)
    const int gr0   = grp * 32;

    // ---- h0: ha -> bf16 hi/lo tiles + hold slots ----
    for (int j = tid; j < 8192; j += NTHR) {
        int r = j >> 7, u = j & 127;
        float v = ha[r*HPAD + u];
        __nv_bfloat16 bh = __float2bfloat16(v);
        __nv_bfloat16 bl = __float2bfloat16(v - __bfloat162float(bh));
        *(__nv_bfloat16*)(hhi + r*272 + u*2) = bh;
        *(__nv_bfloat16*)(hlo + r*272 + u*2) = bl;
    }
    #pragma unroll
    for (int i = 0; i < 2; ++i)
        #pragma unroll
        for (int nt = 0; nt < 4; ++nt)
            #pragma unroll
            for (int j = 0; j < 2; ++j) {
                int u = wm*16 + (lane >> 2) + 8*i;
                int r = gr0 + nt*8 + (lane & 3)*2 + j;
                hs[(i*8 + nt*2 + j)*512 + tid] = ha[r*HPAD + u];
            }
    __syncthreads();
    const float db1v = sm[F_DB1];
    const uint4* wf = g_wfrag;

    // decoder (warps wm<4 of each group): reads tiles of own rows -> out col + xps
    auto decoder = [&](int col) {
        float dacc[4] = {0.0f, 0.0f, 0.0f, 0.0f};
        #pragma unroll
        for (int k = 0; k < 8; ++k) {
            int r = gr0 + wm*8 + (lane >> 2);
            int off = r*272 + k*32 + (lane & 3)*4;
            u32 b0 = *(const u32*)(hhi + off);
            u32 b1 = *(const u32*)(hhi + off + 16);
            u32 c0 = *(const u32*)(hlo + off);
            u32 c1 = *(const u32*)(hlo + off + 16);
            uint4 ah = __ldg(&g_dfrag[k*32 + lane]);
            uint4 al = __ldg(&g_dfrag[256 + k*32 + lane]);
            MMA(dacc, ah, b0, b1);
            MMA(dacc, ah, c0, c1);
            MMA(dacc, al, b0, b1);
        }
        int i = lane >> 2;
        float w1a = dw1s[i], w1b = dw1s[i + 8];
        float b0a = db0s[i], b0b = db0s[i + 8];
        float v0 = fmaxf(dacc[0] + b0a, 0.0f)*w1a + fmaxf(dacc[2] + b0b, 0.0f)*w1b;
        float v1 = fmaxf(dacc[1] + b0a, 0.0f)*w1a + fmaxf(dacc[3] + b0b, 0.0f)*w1b;
        v0 += __shfl_xor_sync(0xffffffffu, v0, 4);
        v0 += __shfl_xor_sync(0xffffffffu, v0, 8);
        v0 += __shfl_xor_sync(0xffffffffu, v0, 16);
        v1 += __shfl_xor_sync(0xffffffffu, v1, 4);
        v1 += __shfl_xor_sync(0xffffffffu, v1, 8);
        v1 += __shfl_xor_sync(0xffffffffu, v1, 16);
        if (lane < 4) {
            int r0 = gr0 + wm*8 + lane*2;
            float o0 = v0 + db1v;
            float o1 = v1 + db1v;
            out[(u64)(row0 + r0)*50 + col] = o0;
            out[(u64)(row0 + r0 + 1)*50 + col] = o1;
            xps[r0]     = o0;
            xps[r0 + 1] = o1;
        }
    };

    float acc[3][4][4];

    // phase A: decoder (s>=1) + GRU MMA over this group's 32 rows
    auto phaseA = [&](int s) {
        if (s > 0 && wm < 4) decoder(s);
        #pragma unroll
        for (int g = 0; g < 3; ++g)
            #pragma unroll
            for (int nt = 0; nt < 4; ++nt)
                #pragma unroll
                for (int q = 0; q < 4; ++q) acc[g][nt][q] = 0.0f;
        #pragma unroll 2
        for (int k = 0; k < 8; ++k) {
            u32 bh[4][2], bl[4][2];
            #pragma unroll
            for (int nt = 0; nt < 4; ++nt) {
                int r = gr0 + nt*8 + (lane >> 2);
                int off = r*272 + k*32 + (lane & 3)*4;
                bh[nt][0] = *(const u32*)(hhi + off);
                bh[nt][1] = *(const u32*)(hhi + off + 16);
                bl[nt][0] = *(const u32*)(hlo + off);
                bl[nt][1] = *(const u32*)(hlo + off + 16);
            }
            #pragma unroll
            for (int g = 0; g < 3; ++g) {
                uint4 ah = __ldg(&wf[(g*8 + wm)*256 + k*32 + lane]);
                uint4 al = __ldg(&wf[6144 + (g*8 + wm)*256 + k*32 + lane]);
                #pragma unroll
                for (int nt = 0; nt < 4; ++nt) {
                    MMA(acc[g][nt], ah, bh[nt][0], bh[nt][1]);
                    MMA(acc[g][nt], ah, bl[nt][0], bl[nt][1]);
                    MMA(acc[g][nt], al, bh[nt][0], bh[nt][1]);
                }
            }
        }
    };

    // phase B: epilogue -> new h, write tiles + hold slots (group rows only)
    auto phaseB = [&]() {
        #pragma unroll
        for (int i = 0; i < 2; ++i) {
            int u = wm*16 + (lane >> 2) + 8*i;
            float wir = wihs[u], wiz = wihs[128 + u], win = wihs[256 + u];
            float br  = bihs[u]       + bhhs[u];
            float bz  = bihs[128 + u] + bhhs[128 + u];
            float bni = bihs[256 + u];
            float bnh = bhhs[256 + u];
            #pragma unroll
            for (int nt = 0; nt < 4; ++nt) {
                #pragma unroll
                for (int j = 0; j < 2; ++j) {
                    int r = gr0 + nt*8 + (lane & 3)*2 + j;
                    int q = 2*i + j;
                    int hidx = (i*8 + nt*2 + j)*512 + tid;
                    float xp   = xps[r];
                    float hold = hs[hidx];
                    float rg = sigm(acc[0][nt][q] + fmaf(xp, wir, br));
                    float zg = sigm(acc[1][nt][q] + fmaf(xp, wiz, bz));
                    float ng = tanha(fmaf(xp, win, bni) + rg*(acc[2][nt][q] + bnh));
                    float h  = (1.0f - zg)*ng + zg*hold;
                    hs[hidx] = h;
                    __nv_bfloat16 bhv = __float2bfloat16(h);
                    __nv_bfloat16 blv = __float2bfloat16(h - __bfloat162float(bhv));
                    *(__nv_bfloat16*)(hhi + r*272 + u*2) = bhv;
                    *(__nv_bfloat16*)(hlo + r*272 + u*2) = blv;
                }
            }
        }
    };

    if (grp == 0) {
        // skewed pipeline: MMA(0) first, loop = [epi(s); MMA(s+1)]
        phaseA(0);
        for (int s = 0; s < NSTEP; ++s) {
            BARG(0);
            phaseB();
            BARG(0);
            if (s < NSTEP - 1) phaseA(s + 1);
        }
        if (wm < 4) decoder(NSTEP);
    } else {
        // natural order: loop = [MMA(s); epi(s)]
        for (int s = 0; s < NSTEP; ++s) {
            phaseA(s);
            BARG(1);
            phaseB();
            BARG(1);
        }
        if (wm < 4) decoder(NSTEP);
    }
}

extern "C" void kernel_launch(void* const* d_in, const int* in_sizes, int n_in,
                              void* d_out, int out_size) {
    (void)in_sizes; (void)n_in; (void)out_size;
    const float* x   = (const float*)d_in[0];
    const float* ew0 = (const float*)d_in[1];
    const float* eb0 = (const float*)d_in[2];
    const float* ew1 = (const float*)d_in[3];
    const float* eb1 = (const float*)d_in[4];
    const float* ew2 = (const float*)d_in[5];
    const float* eb2 = (const float*)d_in[6];
    const float* wih = (const float*)d_in[7];
    const float* whh = (const float*)d_in[8];
    const float* bih = (const float*)d_in[9];
    const float* bhh = (const float*)d_in[10];
    const float* dw0 = (const float*)d_in[11];
    const float* db0 = (const float*)d_in[12];
    const float* dw1 = (const float*)d_in[13];
    const float* db1 = (const float*)d_in[14];
    float* out = (float*)d_out;

    cudaFuncSetAttribute(gru_kernel, cudaFuncAttributeMaxDynamicSharedMemorySize, SMEM_BYTES);

    repack<<<25, 512>>>(whh, dw0);
    gru_kernel<<<NBLK, NTHR, SMEM_BYTES>>>(x, ew0, eb0, ew1, eb1, ew2, eb2,
                                           wih, whh, bih, bhh, dw0, db0, dw1, db1, out);
}